// round 11
// baseline (speedup 1.0000x reference)
#include <cuda_runtime.h>
#include <cuda_fp16.h>
#include <math.h>
#include <stdint.h>

#define B_    2
#define N_    6
#define FD    128
#define DIM   128
#define H_    64
#define W_    176
#define P_    (H_*W_)          // 11264
#define BNV   (B_*N_)          // 12
#define T2    (B_*P_)          // 22528
#define IMG_W_ 704.0f
#define IMG_H_ 256.0f

// conv chunk tiles: rows x 32 fp16, padded to 40 (80 B rows)
#define TPAD40   40
#define TROWB40  80
#define APLANE40 (128*TPAD40)            // 5120
#define BPLANE40 (64*TPAD40)             // 2560
#define CONV_STAGE (APLANE40 + 2*BPLANE40)   // 10240 halves
#define SMEM_CONV (2*CONV_STAGE*2)       // 40960 B, 2-stage ring
// mlp tiles: rows x 64 fp16, padded to 72 (144 B rows)
#define TPAD72   72
#define TROWB72  144
#define SMEM_MLP1 ((128+64+64)*TPAD72*2)     // 36864 B
#define SMEM_MLP2 ((64+128+128)*TPAD72*2)    // 46080 B

// ---------------- scratch ----------------
__device__ float  g_Hm[BNV*9];
__device__ float  g_bns[FD];
__device__ float  g_bnt[FD];
__device__ __half g_wch[DIM*FD],      g_wcl[DIM*FD];       // conv W [o][c] split
__device__ __half g_w1h[(2*DIM)*DIM], g_w1l[(2*DIM)*DIM];  // w1^T [j][c] split
__device__ __half g_w2h[DIM*(2*DIM)], g_w2l[DIM*(2*DIM)];  // w2^T [d][j] split
__device__ __half g_valh[(size_t)BNV*P_*DIM];              // conv out fp16 (gathers)
__device__ float  g_q[(size_t)B_*P_*DIM];                  // conv out fp32, n=0 only (query)
__device__ float  g_zln[(size_t)T2*DIM];                   // post-LN1 fp32 (residual)
__device__ __half g_zh[(size_t)T2*DIM];                    // post-LN1 fp16 (mlp1 A)
__device__ __half g_hh[(size_t)T2*(2*DIM)];                // hidden fp16 (mlp2 A)

// ---------------- helpers ----------------
__device__ __forceinline__ float wsum(float v) {
    #pragma unroll
    for (int o = 16; o > 0; o >>= 1) v += __shfl_xor_sync(0xFFFFFFFFu, v, o);
    return v;
}
__device__ __forceinline__ float gelu_exact(float x) {
    return 0.5f * x * (1.0f + erff(x * 0.70710678118654752f));
}
__device__ __forceinline__ uint32_t pack2h(__half a, __half b) {
    return (uint32_t)__half_as_ushort(a) | ((uint32_t)__half_as_ushort(b) << 16);
}

// ---------------- async copy ----------------
__device__ __forceinline__ void cpa16(uint32_t s, const void* g) {
    asm volatile("cp.async.cg.shared.global [%0], [%1], 16;" :: "r"(s), "l"(g));
}
__device__ __forceinline__ void cpa_commit() { asm volatile("cp.async.commit_group;"); }
__device__ __forceinline__ void cpa_wait0()  { asm volatile("cp.async.wait_group 0;"); }

// rows x 64 fp16 chunk of a row-major plane -> 144B-stride smem tile
__device__ __forceinline__ void load_rows72(const __half* g, int rstride, int c0,
                                            __half* sm, int rows, int t) {
    uint32_t sb = (uint32_t)__cvta_generic_to_shared(sm);
    for (int i = t; i < rows*8; i += 256) {
        int row = i >> 3, seg = i & 7;
        cpa16(sb + row*TROWB72 + seg*16, g + (size_t)row*rstride + c0 + seg*8);
    }
}
// 64 x 32 fp16 chunk -> 80B-stride smem tile (1 cp.async/thread)
__device__ __forceinline__ void load_b64_40(const __half* g, int rstride, int c0,
                                            __half* sm, int t) {
    uint32_t sb = (uint32_t)__cvta_generic_to_shared(sm);
    int row = t >> 2, seg = t & 3;
    cpa16(sb + row*TROWB40 + seg*16, g + (size_t)row*rstride + c0 + seg*8);
}

// ---------------- warp-mma primitives ----------------
__device__ __forceinline__ void ldsm4(uint32_t* r, uint32_t addr) {
    asm volatile("ldmatrix.sync.aligned.m8n8.x4.shared.b16 {%0,%1,%2,%3}, [%4];"
        : "=r"(r[0]), "=r"(r[1]), "=r"(r[2]), "=r"(r[3]) : "r"(addr));
}
__device__ __forceinline__ void ldsm2(uint32_t* r, uint32_t addr) {
    asm volatile("ldmatrix.sync.aligned.m8n8.x2.shared.b16 {%0,%1}, [%2];"
        : "=r"(r[0]), "=r"(r[1]) : "r"(addr));
}
__device__ __forceinline__ void mma_f16(float* d, const uint32_t* a, const uint32_t* b) {
    asm volatile("mma.sync.aligned.m16n8k16.row.col.f32.f16.f16.f32 "
        "{%0,%1,%2,%3}, {%4,%5,%6,%7}, {%8,%9}, {%0,%1,%2,%3};"
        : "+f"(d[0]), "+f"(d[1]), "+f"(d[2]), "+f"(d[3])
        : "r"(a[0]), "r"(a[1]), "r"(a[2]), "r"(a[3]), "r"(b[0]), "r"(b[1]));
}

// K=32 chunk, warp tile 32x32, 80B stride: acc += A*(Bh^T+Bl^T)
__device__ __forceinline__ void gemm32_w32(float acc[2][4][4],
                                           const __half* sA, const __half* sBh,
                                           const __half* sBl, int wm, int wn, int lane) {
    uint32_t aB = (uint32_t)__cvta_generic_to_shared(sA);
    uint32_t bH = (uint32_t)__cvta_generic_to_shared(sBh);
    uint32_t bL = (uint32_t)__cvta_generic_to_shared(sBl);
    uint32_t aoff = (uint32_t)(wm + (lane & 15)) * TROWB40 + ((lane >> 4) << 4);
    uint32_t boff = (uint32_t)(wn + (lane & 7))  * TROWB40 + (((lane >> 3) & 1) << 4);
    #pragma unroll
    for (int kk = 0; kk < 2; kk++) {
        uint32_t kb = (uint32_t)kk * 32;
        uint32_t ah[2][4], bh[4][2], bl[4][2];
        #pragma unroll
        for (int mt = 0; mt < 2; mt++)
            ldsm4(ah[mt], aB + aoff + (uint32_t)mt*16*TROWB40 + kb);
        #pragma unroll
        for (int nt = 0; nt < 4; nt++) {
            uint32_t o = boff + (uint32_t)nt*8*TROWB40 + kb;
            ldsm2(bh[nt], bH + o);
            ldsm2(bl[nt], bL + o);
        }
        #pragma unroll
        for (int mt = 0; mt < 2; mt++)
            #pragma unroll
            for (int nt = 0; nt < 4; nt++) {
                mma_f16(acc[mt][nt], ah[mt], bh[nt]);
                mma_f16(acc[mt][nt], ah[mt], bl[nt]);
            }
    }
}

// K=64 chunk, warp tile 32x32, 144B stride
__device__ __forceinline__ void gemm64_w32(float acc[2][4][4],
                                           const __half* sA, const __half* sBh,
                                           const __half* sBl, int wm, int wn, int lane) {
    uint32_t aB = (uint32_t)__cvta_generic_to_shared(sA);
    uint32_t bH = (uint32_t)__cvta_generic_to_shared(sBh);
    uint32_t bL = (uint32_t)__cvta_generic_to_shared(sBl);
    uint32_t aoff = (uint32_t)(wm + (lane & 15)) * TROWB72 + ((lane >> 4) << 4);
    uint32_t boff = (uint32_t)(wn + (lane & 7))  * TROWB72 + (((lane >> 3) & 1) << 4);
    #pragma unroll
    for (int kk = 0; kk < 4; kk++) {
        uint32_t kb = (uint32_t)kk * 32;
        uint32_t ah[2][4], bh[4][2], bl[4][2];
        #pragma unroll
        for (int mt = 0; mt < 2; mt++)
            ldsm4(ah[mt], aB + aoff + (uint32_t)mt*16*TROWB72 + kb);
        #pragma unroll
        for (int nt = 0; nt < 4; nt++) {
            uint32_t o = boff + (uint32_t)nt*8*TROWB72 + kb;
            ldsm2(bh[nt], bH + o);
            ldsm2(bl[nt], bL + o);
        }
        #pragma unroll
        for (int mt = 0; mt < 2; mt++)
            #pragma unroll
            for (int nt = 0; nt < 4; nt++) {
                mma_f16(acc[mt][nt], ah[mt], bh[nt]);
                mma_f16(acc[mt][nt], ah[mt], bl[nt]);
            }
    }
}

// ---------------- K0: setup ----------------
__global__ void k_setup(const float* __restrict__ I_src, const float* __restrict__ I_tar_inv,
                        const float* __restrict__ E, const float* __restrict__ dis,
                        const float* __restrict__ nrm, const float* __restrict__ conv_w,
                        const float* __restrict__ bg, const float* __restrict__ bb,
                        const float* __restrict__ bm, const float* __restrict__ bv,
                        const float* __restrict__ w1, const float* __restrict__ w2) {
    int t = threadIdx.x;
    if (blockIdx.x == 0) {
        if (t < BNV) {
            int b = t / N_;
            float ds = dis[b];
            float M[9], A[9];
            #pragma unroll
            for (int i = 0; i < 3; i++) {
                float Ti = E[t*16 + i*4 + 3];
                #pragma unroll
                for (int j = 0; j < 3; j++)
                    M[i*3+j] = E[t*16 + i*4 + j] - Ti * nrm[b*3+j] / ds;
            }
            #pragma unroll
            for (int i = 0; i < 3; i++)
                #pragma unroll
                for (int j = 0; j < 3; j++) {
                    float s = 0.f;
                    #pragma unroll
                    for (int k = 0; k < 3; k++) s += I_src[t*9 + i*3 + k] * M[k*3+j];
                    A[i*3+j] = s;
                }
            #pragma unroll
            for (int i = 0; i < 3; i++)
                #pragma unroll
                for (int j = 0; j < 3; j++) {
                    float s = 0.f;
                    #pragma unroll
                    for (int k = 0; k < 3; k++) s += A[i*3+k] * I_tar_inv[b*9 + k*3 + j];
                    g_Hm[t*9 + i*3 + j] = s;
                }
        }
        if (t < FD) {
            float s = bg[t] / sqrtf(bv[t] + 1e-5f);
            g_bns[t] = s;
            g_bnt[t] = bb[t] - bm[t] * s;
        }
    }
    int g = blockIdx.x * blockDim.x + t;
    int stride = gridDim.x * blockDim.x;
    for (int i = g; i < DIM*FD; i += stride) {
        float w = conv_w[i];
        __half h = __float2half(w);
        g_wch[i] = h;
        g_wcl[i] = __float2half(w - __half2float(h));
    }
    for (int i = g; i < (2*DIM)*DIM; i += stride) {
        int j = i >> 7, c = i & 127;
        float w = w1[c*(2*DIM) + j];
        __half h = __float2half(w);
        g_w1h[i] = h;
        g_w1l[i] = __float2half(w - __half2float(h));
    }
    for (int i = g; i < DIM*(2*DIM); i += stride) {
        int d = i >> 8, j = i & 255;
        float w = w2[j*DIM + d];
        __half h = __float2half(w);
        g_w2h[i] = h;
        g_w2l[i] = __float2half(w - __half2float(h));
    }
}

// ---------------- K1: conv GEMM (CTA 128p x 64o, 3 CTAs/SM, pipelined) ----------------
__global__ void __launch_bounds__(256, 3) k_conv_tc(const float* __restrict__ feat) {
    extern __shared__ __half smh[];
    __half* stage[2] = { smh, smh + CONV_STAGE };
    int t = threadIdx.x, wid = t >> 5, lane = t & 31;
    int bn = blockIdx.y;
    int ohalf = blockIdx.x & 1;                 // low bit: adjacent CTAs share A tile
    int p0 = (blockIdx.x >> 1) * 128;
    int o0 = ohalf * 64;

    float acc[2][4][4] = {};
    int wm = (wid >> 1) * 32;                   // 4 m-groups over 128 pixels
    int wn = (wid & 1) * 32;                    // 2 n-groups over 64 outputs
    const float* fb = feat + (size_t)bn * FD * P_ + p0;
    const __half* Bh = g_wch + (size_t)o0 * FD;
    const __half* Bl = g_wcl + (size_t)o0 * FD;
    int ap  = t & 127;                          // pixel
    int acb = (t >> 7) * 16;                    // 16-channel base within chunk

    float rA[16];
    #pragma unroll
    for (int k = 0; k < 16; k++) {
        int c = acb + k;
        rA[k] = fmaxf(fmaf(fb[(size_t)c * P_ + ap], g_bns[c], g_bnt[c]), 0.f);
    }
    load_b64_40(Bh, FD, 0, stage[0] + APLANE40, t);
    load_b64_40(Bl, FD, 0, stage[0] + APLANE40 + BPLANE40, t);
    cpa_commit();

    #pragma unroll 1
    for (int i = 0; i < 4; i++) {
        cpa_wait0();
        {
            __half* sA = stage[i & 1];
            #pragma unroll
            for (int j = 0; j < 8; j++)
                *(uint32_t*)&sA[ap*TPAD40 + acb + 2*j] =
                    pack2h(__float2half(rA[2*j]), __float2half(rA[2*j+1]));
        }
        if (i < 3) {
            int c0n = (i + 1) * 32;
            #pragma unroll
            for (int k = 0; k < 16; k++) {
                int c = c0n + acb + k;
                rA[k] = fmaxf(fmaf(fb[(size_t)c * P_ + ap], g_bns[c], g_bnt[c]), 0.f);
            }
        }
        __syncthreads();
        if (i < 3) {
            int c0n = (i + 1) * 32;
            load_b64_40(Bh, FD, c0n, stage[(i+1) & 1] + APLANE40, t);
            load_b64_40(Bl, FD, c0n, stage[(i+1) & 1] + APLANE40 + BPLANE40, t);
            cpa_commit();
        }
        gemm32_w32(acc, stage[i & 1], stage[i & 1] + APLANE40,
                   stage[i & 1] + APLANE40 + BPLANE40, wm, wn, lane);
    }

    __half* dsth = g_valh + ((size_t)bn * P_ + p0) * DIM + o0;
    int r0 = wm + (lane >> 2);
    int c0g = wn + (lane & 3) * 2;
    bool isq = (bn % N_) == 0;
    float* dq = g_q + ((size_t)(bn / N_) * P_ + p0) * DIM + o0;
    #pragma unroll
    for (int mt = 0; mt < 2; mt++)
        #pragma unroll
        for (int nt = 0; nt < 4; nt++) {
            int row = r0 + mt*16, col = c0g + nt*8;
            *(uint32_t*)&dsth[(size_t)row*DIM + col] =
                pack2h(__float2half(acc[mt][nt][0]), __float2half(acc[mt][nt][1]));
            *(uint32_t*)&dsth[(size_t)(row+8)*DIM + col] =
                pack2h(__float2half(acc[mt][nt][2]), __float2half(acc[mt][nt][3]));
            if (isq) {
                *(float2*)&dq[(size_t)row*DIM + col]     = make_float2(acc[mt][nt][0], acc[mt][nt][1]);
                *(float2*)&dq[(size_t)(row+8)*DIM + col] = make_float2(acc[mt][nt][2], acc[mt][nt][3]);
            }
        }
}

// ---------------- K2: uv + bilinear (fp16 gathers) + attention + residual + LN1 ----------------
__global__ void __launch_bounds__(256) k_attn(const float* __restrict__ ln1g,
                                              const float* __restrict__ ln1b) {
    __shared__ float sHm[BNV*9];
    int t = threadIdx.x;
    if (t < BNV*9) sHm[t] = g_Hm[t];
    __syncthreads();

    int warp = t >> 5, lane = t & 31;
    int pix = blockIdx.x * 8 + warp;
    int b = pix / P_;
    int p = pix - b * P_;
    int x = p % W_, y = p / W_;
    float px = ((float)x / (float)(W_-1)) * IMG_W_;
    float py = ((float)y / (float)(H_-1)) * IMG_H_;
    int d0 = lane << 2;

    const float4 q4 = *(const float4*)&g_q[((size_t)b*P_ + p) * DIM + d0];
    float qs = q4.x*q4.x + q4.y*q4.y + q4.z*q4.z + q4.w*q4.w;

    float vb[N_][4];
    float ssv[N_], ddv[N_], valid[N_];
    #pragma unroll
    for (int n = 0; n < N_; n++) {
        int bn = b*N_ + n;
        const float* Hm = &sHm[bn*9];
        float hx = Hm[0]*px + Hm[1]*py + Hm[2];
        float hy = Hm[3]*px + Hm[4]*py + Hm[5];
        float hz = Hm[6]*px + Hm[7]*py + Hm[8];
        float ux = ((hx / hz) / IMG_W_) * (float)W_;
        float uy = ((hy / hz) / IMG_H_) * (float)H_;
        float fx = floorf(ux), fy = floorf(uy);
        float wx = ux - fx,  wy = uy - fy;
        valid[n] = (ux >= 0.f && ux <= (float)(W_-1) &&
                    uy >= 0.f && uy <= (float)(H_-1)) ? 1.0f : 0.0f;
        int x0 = min(max((int)fx, 0), W_-1);
        int x1 = min(x0+1, W_-1);
        int y0 = min(max((int)fy, 0), H_-1);
        int y1 = min(y0+1, H_-1);
        float w00 = (1.f-wx)*(1.f-wy), w01 = wx*(1.f-wy);
        float w10 = (1.f-wx)*wy,       w11 = wx*wy;
        const __half* baseh = g_valh + (size_t)bn*P_*DIM + d0;
        uint2 u00 = *(const uint2*)&baseh[(size_t)(y0*W_+x0)*DIM];
        uint2 u01 = *(const uint2*)&baseh[(size_t)(y0*W_+x1)*DIM];
        uint2 u10 = *(const uint2*)&baseh[(size_t)(y1*W_+x0)*DIM];
        uint2 u11 = *(const uint2*)&baseh[(size_t)(y1*W_+x1)*DIM];
        float2 a00a = __half22float2(*(__half2*)&u00.x), a00b = __half22float2(*(__half2*)&u00.y);
        float2 a01a = __half22float2(*(__half2*)&u01.x), a01b = __half22float2(*(__half2*)&u01.y);
        float2 a10a = __half22float2(*(__half2*)&u10.x), a10b = __half22float2(*(__half2*)&u10.y);
        float2 a11a = __half22float2(*(__half2*)&u11.x), a11b = __half22float2(*(__half2*)&u11.y);
        float v0 = a00a.x*w00 + a01a.x*w01 + a10a.x*w10 + a11a.x*w11;
        float v1 = a00a.y*w00 + a01a.y*w01 + a10a.y*w10 + a11a.y*w11;
        float v2 = a00b.x*w00 + a01b.x*w01 + a10b.x*w10 + a11b.x*w11;
        float v3 = a00b.y*w00 + a01b.y*w01 + a10b.y*w10 + a11b.y*w11;
        vb[n][0] = v0; vb[n][1] = v1; vb[n][2] = v2; vb[n][3] = v3;
        ssv[n] = v0*v0 + v1*v1 + v2*v2 + v3*v3;
        ddv[n] = q4.x*v0 + q4.y*v1 + q4.z*v2 + q4.w*v3;
    }
    qs = wsum(qs);
    #pragma unroll
    for (int n = 0; n < N_; n++) { ssv[n] = wsum(ssv[n]); ddv[n] = wsum(ddv[n]); }
    float qinv = 1.0f / fmaxf(sqrtf(qs), 1e-12f);
    float dot[N_];
    #pragma unroll
    for (int n = 0; n < N_; n++)
        dot[n] = ddv[n] * qinv * (1.0f / fmaxf(sqrtf(ssv[n]), 1e-12f)) * valid[n];

    float m = dot[0];
    #pragma unroll
    for (int n = 1; n < N_; n++) m = fmaxf(m, dot[n]);
    float e[N_], s = 0.f;
    #pragma unroll
    for (int n = 0; n < N_; n++) { e[n] = expf(dot[n] - m); s += e[n]; }
    float sinv = 1.0f / s;
    float z[4] = {q4.x, q4.y, q4.z, q4.w};
    #pragma unroll
    for (int n = 0; n < N_; n++) {
        float a = e[n] * sinv;
        #pragma unroll
        for (int i = 0; i < 4; i++) z[i] = fmaf(a, vb[n][i], z[i]);
    }
    float ls = z[0] + z[1] + z[2] + z[3];
    ls = wsum(ls);
    float mean = ls * (1.0f / DIM);
    float vv = 0.f;
    #pragma unroll
    for (int i = 0; i < 4; i++) { float d = z[i] - mean; vv += d*d; }
    vv = wsum(vv);
    float rstd = 1.0f / sqrtf(vv * (1.0f / DIM) + 1e-5f);
    float4 g4 = *(const float4*)&ln1g[d0];
    float4 b4 = *(const float4*)&ln1b[d0];
    float zn[4];
    zn[0] = (z[0]-mean)*rstd*g4.x + b4.x;
    zn[1] = (z[1]-mean)*rstd*g4.y + b4.y;
    zn[2] = (z[2]-mean)*rstd*g4.z + b4.z;
    zn[3] = (z[3]-mean)*rstd*g4.w + b4.w;
    *(float4*)&g_zln[(size_t)pix*DIM + d0] = make_float4(zn[0], zn[1], zn[2], zn[3]);
    *(uint2*)&g_zh[(size_t)pix*DIM + d0] =
        make_uint2(pack2h(__float2half(zn[0]), __float2half(zn[1])),
                   pack2h(__float2half(zn[2]), __float2half(zn[3])));
}

// ---------------- K3: MLP1 (CTA 128tok x 64j, 3 CTAs/SM) ----------------
__global__ void __launch_bounds__(256, 3) k_mlp1_tc(const float* __restrict__ b1) {
    extern __shared__ __half smh[];
    __half* sA  = smh;                  // 128 x 72
    __half* sBh = smh + 128*TPAD72;     // 64 x 72
    __half* sBl = sBh + 64*TPAD72;      // 64 x 72
    int t = threadIdx.x, wid = t >> 5, lane = t & 31;
    int t0 = blockIdx.x * 128;
    int j0 = blockIdx.y * 64;

    float acc[2][4][4] = {};
    int wm = (wid >> 1) * 32;
    int wn = (wid & 1) * 32;
    const __half* Ag = g_zh + (size_t)t0 * DIM;
    const __half* Bh = g_w1h + (size_t)j0 * DIM;
    const __half* Bl = g_w1l + (size_t)j0 * DIM;

    #pragma unroll 1
    for (int c = 0; c < 2; c++) {
        if (c) __syncthreads();
        int c0 = c * 64;
        load_rows72(Ag, DIM, c0, sA, 128, t);
        load_rows72(Bh, DIM, c0, sBh, 64, t);
        load_rows72(Bl, DIM, c0, sBl, 64, t);
        cpa_commit();
        cpa_wait0();
        __syncthreads();
        gemm64_w32(acc, sA, sBh, sBl, wm, wn, lane);
    }

    int r0 = wm + (lane >> 2);
    int c0 = wn + (lane & 3) * 2;
    #pragma unroll
    for (int mt = 0; mt < 2; mt++)
        #pragma unroll
        for (int nt = 0; nt < 4; nt++) {
            int row = r0 + mt*16, col = c0 + nt*8;
            float bj0 = b1[j0 + col], bj1 = b1[j0 + col + 1];
            float v00 = gelu_exact(acc[mt][nt][0] + bj0);
            float v01 = gelu_exact(acc[mt][nt][1] + bj1);
            float v10 = gelu_exact(acc[mt][nt][2] + bj0);
            float v11 = gelu_exact(acc[mt][nt][3] + bj1);
            *(uint32_t*)&g_hh[(size_t)(t0+row)*(2*DIM) + j0 + col] =
                pack2h(__float2half(v00), __float2half(v01));
            *(uint32_t*)&g_hh[(size_t)(t0+row+8)*(2*DIM) + j0 + col] =
                pack2h(__float2half(v10), __float2half(v11));
        }
}

// ---------------- K4: MLP2 (CTA 64tok x 128d, 3 CTAs/SM) + residual + LN2 ----------------
__global__ void __launch_bounds__(256, 3) k_mlp2_tc(const float* __restrict__ b2,
                                                    const float* __restrict__ g2,
                                                    const float* __restrict__ bb2,
                                                    float* __restrict__ out) {
    extern __shared__ __half smh[];
    __half* sA  = smh;                  // 64 x 72
    __half* sBh = smh + 64*TPAD72;      // 128 x 72
    __half* sBl = sBh + 128*TPAD72;     // 128 x 72
    int t = threadIdx.x, wid = t >> 5, lane = t & 31;
    int t0 = blockIdx.x * 64;

    float acc[2][4][4] = {};
    int wm = (wid >> 2) * 32;
    int wn = (wid & 3) * 32;
    const __half* Ag = g_hh + (size_t)t0 * (2*DIM);

    #pragma unroll 1
    for (int c = 0; c < 4; c++) {
        if (c) __syncthreads();
        int c0 = c * 64;
        load_rows72(Ag,    2*DIM, c0, sA,   64, t);
        load_rows72(g_w2h, 2*DIM, c0, sBh, 128, t);
        load_rows72(g_w2l, 2*DIM, c0, sBl, 128, t);
        cpa_commit();
        cpa_wait0();
        __syncthreads();
        gemm64_w32(acc, sA, sBh, sBl, wm, wn, lane);
    }
    __syncthreads();   // smem reuse

    float* smT   = (float*)smh;         // [64][129] fp32
    float* sMean = smT + 64*129;
    float* sRstd = sMean + 64;
    const float* zb = g_zln + (size_t)t0 * DIM;
    int r0 = wm + (lane >> 2);
    int c0 = wn + (lane & 3) * 2;
    #pragma unroll
    for (int mt = 0; mt < 2; mt++)
        #pragma unroll
        for (int nt = 0; nt < 4; nt++) {
            int row = r0 + mt*16, col = c0 + nt*8;
            float b20 = b2[col], b21 = b2[col+1];
            float2 z0 = *(const float2*)&zb[(size_t)row*DIM + col];
            float2 z1 = *(const float2*)&zb[(size_t)(row+8)*DIM + col];
            smT[row*129 + col]       = acc[mt][nt][0] + b20 + z0.x;
            smT[row*129 + col + 1]   = acc[mt][nt][1] + b21 + z0.y;
            smT[(row+8)*129 + col]   = acc[mt][nt][2] + b20 + z1.x;
            smT[(row+8)*129 + col+1] = acc[mt][nt][3] + b21 + z1.y;
        }
    __syncthreads();
    if (t < 64) {
        float s = 0.f, q = 0.f;
        #pragma unroll 8
        for (int c = 0; c < 128; c++) {
            float v = smT[t*129 + c];
            s += v; q += v*v;
        }
        float mean = s * (1.0f / DIM);
        float var  = fmaxf(q * (1.0f / DIM) - mean*mean, 0.0f);
        sMean[t] = mean;
        sRstd[t] = 1.0f / sqrtf(var + 1e-5f);
    }
    __syncthreads();
    int b = t0 / P_;
    int prem = t0 - b * P_;
    #pragma unroll 4
    for (int k = 0; k < 32; k++) {
        int idx = k * 256 + t;
        int d = idx >> 6, p = idx & 63;   // consecutive t -> consecutive p
        float v = smT[p*129 + d];
        out[((size_t)(b*DIM + d))*P_ + prem + p] =
            (v - sMean[p]) * sRstd[p] * g2[d] + bb2[d];
    }
}

// ---------------- launch ----------------
extern "C" void kernel_launch(void* const* d_in, const int* in_sizes, int n_in,
                              void* d_out, int out_size) {
    const float* feature   = (const float*)d_in[0];
    const float* I_src     = (const float*)d_in[1];
    const float* I_tar_inv = (const float*)d_in[2];
    const float* E         = (const float*)d_in[3];
    const float* dis       = (const float*)d_in[4];
    const float* nrm       = (const float*)d_in[5];
    const float* conv_w    = (const float*)d_in[6];
    const float* bn_gamma  = (const float*)d_in[7];
    const float* bn_beta   = (const float*)d_in[8];
    const float* bn_mean   = (const float*)d_in[9];
    const float* bn_var    = (const float*)d_in[10];
    const float* ln1_g     = (const float*)d_in[11];
    const float* ln1_b     = (const float*)d_in[12];
    const float* ln2_g     = (const float*)d_in[13];
    const float* ln2_b     = (const float*)d_in[14];
    const float* mlp_w1    = (const float*)d_in[15];
    const float* mlp_b1    = (const float*)d_in[16];
    const float* mlp_w2    = (const float*)d_in[17];
    const float* mlp_b2    = (const float*)d_in[18];
    float* out = (float*)d_out;

    cudaFuncSetAttribute(k_conv_tc, cudaFuncAttributeMaxDynamicSharedMemorySize, SMEM_CONV);
    cudaFuncSetAttribute(k_mlp1_tc, cudaFuncAttributeMaxDynamicSharedMemorySize, SMEM_MLP1);
    cudaFuncSetAttribute(k_mlp2_tc, cudaFuncAttributeMaxDynamicSharedMemorySize, SMEM_MLP2);

    k_setup<<<48, 256>>>(I_src, I_tar_inv, E, dis, nrm, conv_w,
                         bn_gamma, bn_beta, bn_mean, bn_var, mlp_w1, mlp_w2);
    k_conv_tc<<<dim3((P_/128)*2, BNV), 256, SMEM_CONV>>>(feature);
    k_attn<<<T2/8, 256>>>(ln1_g, ln1_b);
    k_mlp1_tc<<<dim3(T2/128, 4), 256, SMEM_MLP1>>>(mlp_b1);
    k_mlp2_tc<<<T2/64, 256, SMEM_MLP2>>>(mlp_b2, ln2_g, ln2_b, out);
}

// round 12
// speedup vs baseline: 1.0593x; 1.0593x over previous
#include <cuda_runtime.h>
#include <cuda_fp16.h>
#include <math.h>
#include <stdint.h>

#define B_    2
#define N_    6
#define FD    128
#define DIM   128
#define H_    64
#define W_    176
#define P_    (H_*W_)          // 11264
#define BNV   (B_*N_)          // 12
#define T2    (B_*P_)          // 22528
#define IMG_W_ 704.0f
#define IMG_H_ 256.0f

// conv chunk tiles: 128 x 32 fp16, padded to 40 (80 B rows)
#define TPAD40   40
#define TROWB40  80
#define PLANE40  (128*TPAD40)
#define SMEM_CONV (2*3*PLANE40*2)            // 2 stages x (A,Bh,Bl) = 61440 B
// mlp tiles: rows x 64 fp16, padded to 72 (144 B rows)
#define TPAD72   72
#define TROWB72  144
#define SMEM_MLP1 ((128+64+64)*TPAD72*2)     // 36864 B
#define SMEM_MLP2 ((64+128+128)*TPAD72*2)    // 46080 B

// ---------------- scratch ----------------
__device__ float  g_Hm[BNV*9];
__device__ float  g_bns[FD];
__device__ float  g_bnt[FD];
__device__ __half g_wch[DIM*FD],      g_wcl[DIM*FD];       // conv W [o][c] split
__device__ __half g_w1h[(2*DIM)*DIM], g_w1l[(2*DIM)*DIM];  // w1^T [j][c] split
__device__ __half g_w2h[DIM*(2*DIM)], g_w2l[DIM*(2*DIM)];  // w2^T [d][j] split
__device__ __half g_valh[(size_t)BNV*P_*DIM];              // conv out fp16 (gathers)
__device__ float  g_q[(size_t)B_*P_*DIM];                  // conv out fp32, n=0 (query)
__device__ float  g_zln[(size_t)T2*DIM];                   // post-LN1 fp32 (residual)
__device__ __half g_zh[(size_t)T2*DIM];                    // post-LN1 fp16 (mlp1 A)
__device__ __half g_hh[(size_t)T2*(2*DIM)];                // hidden fp16 (mlp2 A)

// ---------------- helpers ----------------
__device__ __forceinline__ float wsum(float v) {
    #pragma unroll
    for (int o = 16; o > 0; o >>= 1) v += __shfl_xor_sync(0xFFFFFFFFu, v, o);
    return v;
}
__device__ __forceinline__ float gelu_exact(float x) {
    return 0.5f * x * (1.0f + erff(x * 0.70710678118654752f));
}
__device__ __forceinline__ uint32_t pack2h(__half a, __half b) {
    return (uint32_t)__half_as_ushort(a) | ((uint32_t)__half_as_ushort(b) << 16);
}

// ---------------- async copy ----------------
__device__ __forceinline__ void cpa16(uint32_t s, const void* g) {
    asm volatile("cp.async.cg.shared.global [%0], [%1], 16;" :: "r"(s), "l"(g));
}
__device__ __forceinline__ void cpa_commit() { asm volatile("cp.async.commit_group;"); }
__device__ __forceinline__ void cpa_wait0()  { asm volatile("cp.async.wait_group 0;"); }

// rows x 64 fp16 chunk of a row-major plane -> 144B-stride smem tile
__device__ __forceinline__ void load_rows72(const __half* g, int rstride, int c0,
                                            __half* sm, int rows, int t) {
    uint32_t sb = (uint32_t)__cvta_generic_to_shared(sm);
    for (int i = t; i < rows*8; i += 256) {
        int row = i >> 3, seg = i & 7;
        cpa16(sb + row*TROWB72 + seg*16, g + (size_t)row*rstride + c0 + seg*8);
    }
}
// 128 x 32 fp16 chunk -> 80B-stride smem tile (2 cp.async/thread)
__device__ __forceinline__ void load_rows40(const __half* g, int rstride, int c0,
                                            __half* sm, int t) {
    uint32_t sb = (uint32_t)__cvta_generic_to_shared(sm);
    #pragma unroll
    for (int k = 0; k < 2; k++) {
        int i = k*256 + t;
        int row = i >> 2, seg = i & 3;
        cpa16(sb + row*TROWB40 + seg*16, g + (size_t)row*rstride + c0 + seg*8);
    }
}

// ---------------- warp-mma primitives ----------------
__device__ __forceinline__ void ldsm4(uint32_t* r, uint32_t addr) {
    asm volatile("ldmatrix.sync.aligned.m8n8.x4.shared.b16 {%0,%1,%2,%3}, [%4];"
        : "=r"(r[0]), "=r"(r[1]), "=r"(r[2]), "=r"(r[3]) : "r"(addr));
}
__device__ __forceinline__ void ldsm2(uint32_t* r, uint32_t addr) {
    asm volatile("ldmatrix.sync.aligned.m8n8.x2.shared.b16 {%0,%1}, [%2];"
        : "=r"(r[0]), "=r"(r[1]) : "r"(addr));
}
__device__ __forceinline__ void mma_f16(float* d, const uint32_t* a, const uint32_t* b) {
    asm volatile("mma.sync.aligned.m16n8k16.row.col.f32.f16.f16.f32 "
        "{%0,%1,%2,%3}, {%4,%5,%6,%7}, {%8,%9}, {%0,%1,%2,%3};"
        : "+f"(d[0]), "+f"(d[1]), "+f"(d[2]), "+f"(d[3])
        : "r"(a[0]), "r"(a[1]), "r"(a[2]), "r"(a[3]), "r"(b[0]), "r"(b[1]));
}

// K=32 chunk, warp tile 64x32 (conv): acc += A*(Bh^T+Bl^T)
__device__ __forceinline__ void gemm32_w64(float acc[4][4][4],
                                           const __half* sA, const __half* sBh,
                                           const __half* sBl, int wm, int wn, int lane) {
    uint32_t aB = (uint32_t)__cvta_generic_to_shared(sA);
    uint32_t bH = (uint32_t)__cvta_generic_to_shared(sBh);
    uint32_t bL = (uint32_t)__cvta_generic_to_shared(sBl);
    uint32_t aoff = (uint32_t)(wm + (lane & 15)) * TROWB40 + ((lane >> 4) << 4);
    uint32_t boff = (uint32_t)(wn + (lane & 7))  * TROWB40 + (((lane >> 3) & 1) << 4);
    #pragma unroll
    for (int kk = 0; kk < 2; kk++) {
        uint32_t kb = (uint32_t)kk * 32;
        uint32_t ah[4][4], bh[4][2], bl[4][2];
        #pragma unroll
        for (int mt = 0; mt < 4; mt++)
            ldsm4(ah[mt], aB + aoff + (uint32_t)mt*16*TROWB40 + kb);
        #pragma unroll
        for (int nt = 0; nt < 4; nt++) {
            uint32_t o = boff + (uint32_t)nt*8*TROWB40 + kb;
            ldsm2(bh[nt], bH + o);
            ldsm2(bl[nt], bL + o);
        }
        #pragma unroll
        for (int mt = 0; mt < 4; mt++)
            #pragma unroll
            for (int nt = 0; nt < 4; nt++) {
                mma_f16(acc[mt][nt], ah[mt], bh[nt]);
                mma_f16(acc[mt][nt], ah[mt], bl[nt]);
            }
    }
}

// K=64 chunk, warp tile 32x32 (mlp1/mlp2)
__device__ __forceinline__ void gemm64_w32(float acc[2][4][4],
                                           const __half* sA, const __half* sBh,
                                           const __half* sBl, int wm, int wn, int lane) {
    uint32_t aB = (uint32_t)__cvta_generic_to_shared(sA);
    uint32_t bH = (uint32_t)__cvta_generic_to_shared(sBh);
    uint32_t bL = (uint32_t)__cvta_generic_to_shared(sBl);
    uint32_t aoff = (uint32_t)(wm + (lane & 15)) * TROWB72 + ((lane >> 4) << 4);
    uint32_t boff = (uint32_t)(wn + (lane & 7))  * TROWB72 + (((lane >> 3) & 1) << 4);
    #pragma unroll
    for (int kk = 0; kk < 4; kk++) {
        uint32_t kb = (uint32_t)kk * 32;
        uint32_t ah[2][4], bh[4][2], bl[4][2];
        #pragma unroll
        for (int mt = 0; mt < 2; mt++)
            ldsm4(ah[mt], aB + aoff + (uint32_t)mt*16*TROWB72 + kb);
        #pragma unroll
        for (int nt = 0; nt < 4; nt++) {
            uint32_t o = boff + (uint32_t)nt*8*TROWB72 + kb;
            ldsm2(bh[nt], bH + o);
            ldsm2(bl[nt], bL + o);
        }
        #pragma unroll
        for (int mt = 0; mt < 2; mt++)
            #pragma unroll
            for (int nt = 0; nt < 4; nt++) {
                mma_f16(acc[mt][nt], ah[mt], bh[nt]);
                mma_f16(acc[mt][nt], ah[mt], bl[nt]);
            }
    }
}

// ---------------- K0: setup ----------------
__global__ void k_setup(const float* __restrict__ I_src, const float* __restrict__ I_tar_inv,
                        const float* __restrict__ E, const float* __restrict__ dis,
                        const float* __restrict__ nrm, const float* __restrict__ conv_w,
                        const float* __restrict__ bg, const float* __restrict__ bb,
                        const float* __restrict__ bm, const float* __restrict__ bv,
                        const float* __restrict__ w1, const float* __restrict__ w2) {
    int t = threadIdx.x;
    if (blockIdx.x == 0) {
        if (t < BNV) {
            int b = t / N_;
            float ds = dis[b];
            float M[9], A[9];
            #pragma unroll
            for (int i = 0; i < 3; i++) {
                float Ti = E[t*16 + i*4 + 3];
                #pragma unroll
                for (int j = 0; j < 3; j++)
                    M[i*3+j] = E[t*16 + i*4 + j] - Ti * nrm[b*3+j] / ds;
            }
            #pragma unroll
            for (int i = 0; i < 3; i++)
                #pragma unroll
                for (int j = 0; j < 3; j++) {
                    float s = 0.f;
                    #pragma unroll
                    for (int k = 0; k < 3; k++) s += I_src[t*9 + i*3 + k] * M[k*3+j];
                    A[i*3+j] = s;
                }
            #pragma unroll
            for (int i = 0; i < 3; i++)
                #pragma unroll
                for (int j = 0; j < 3; j++) {
                    float s = 0.f;
                    #pragma unroll
                    for (int k = 0; k < 3; k++) s += A[i*3+k] * I_tar_inv[b*9 + k*3 + j];
                    g_Hm[t*9 + i*3 + j] = s;
                }
        }
        if (t < FD) {
            float s = bg[t] / sqrtf(bv[t] + 1e-5f);
            g_bns[t] = s;
            g_bnt[t] = bb[t] - bm[t] * s;
        }
    }
    int g = blockIdx.x * blockDim.x + t;
    int stride = gridDim.x * blockDim.x;
    for (int i = g; i < DIM*FD; i += stride) {
        float w = conv_w[i];
        __half h = __float2half(w);
        g_wch[i] = h;
        g_wcl[i] = __float2half(w - __half2float(h));
    }
    for (int i = g; i < (2*DIM)*DIM; i += stride) {
        int j = i >> 7, c = i & 127;
        float w = w1[c*(2*DIM) + j];
        __half h = __float2half(w);
        g_w1h[i] = h;
        g_w1l[i] = __float2half(w - __half2float(h));
    }
    for (int i = g; i < DIM*(2*DIM); i += stride) {
        int d = i >> 8, j = i & 255;
        float w = w2[j*DIM + d];
        __half h = __float2half(w);
        g_w2h[i] = h;
        g_w2l[i] = __float2half(w - __half2float(h));
    }
}

// ---------------- K1: conv GEMM (CTA 128p x 128o, 2 CTAs/SM, pipelined) ----------------
__global__ void __launch_bounds__(256, 2) k_conv_tc(const float* __restrict__ feat) {
    extern __shared__ __half smh[];
    __half* stage[2] = { smh, smh + 3*PLANE40 };
    int t = threadIdx.x, wid = t >> 5, lane = t & 31;
    int bn = blockIdx.y;
    int p0 = blockIdx.x * 128;

    float acc[4][4][4] = {};
    int wm = (wid >> 2) * 64, wn = (wid & 3) * 32;
    const float* fb = feat + (size_t)bn * FD * P_ + p0;
    int ap  = t & 127;               // pixel
    int acb = (t >> 7) * 16;         // 16-channel base within chunk

    float rA[16];
    #pragma unroll
    for (int k = 0; k < 16; k++) {
        int c = acb + k;
        rA[k] = fmaxf(fmaf(fb[(size_t)c * P_ + ap], g_bns[c], g_bnt[c]), 0.f);
    }
    load_rows40(g_wch, FD, 0, stage[0] +   PLANE40, t);
    load_rows40(g_wcl, FD, 0, stage[0] + 2*PLANE40, t);
    cpa_commit();

    #pragma unroll 1
    for (int i = 0; i < 4; i++) {
        cpa_wait0();
        {
            __half* sA = stage[i & 1];
            #pragma unroll
            for (int j = 0; j < 8; j++)
                *(uint32_t*)&sA[ap*TPAD40 + acb + 2*j] =
                    pack2h(__float2half(rA[2*j]), __float2half(rA[2*j+1]));
        }
        if (i < 3) {
            int c0n = (i + 1) * 32;
            #pragma unroll
            for (int k = 0; k < 16; k++) {
                int c = c0n + acb + k;
                rA[k] = fmaxf(fmaf(fb[(size_t)c * P_ + ap], g_bns[c], g_bnt[c]), 0.f);
            }
        }
        __syncthreads();
        if (i < 3) {
            int c0n = (i + 1) * 32;
            load_rows40(g_wch, FD, c0n, stage[(i+1) & 1] +   PLANE40, t);
            load_rows40(g_wcl, FD, c0n, stage[(i+1) & 1] + 2*PLANE40, t);
            cpa_commit();
        }
        gemm32_w64(acc, stage[i & 1], stage[i & 1] + PLANE40, stage[i & 1] + 2*PLANE40,
                   wm, wn, lane);
    }

    __half* dsth = g_valh + ((size_t)bn * P_ + p0) * DIM;
    int r0 = wm + (lane >> 2);
    int c0 = wn + (lane & 3) * 2;
    bool isq = (bn % N_) == 0;
    float* dq = g_q + ((size_t)(bn / N_) * P_ + p0) * DIM;
    #pragma unroll
    for (int mt = 0; mt < 4; mt++)
        #pragma unroll
        for (int nt = 0; nt < 4; nt++) {
            int row = r0 + mt*16, col = c0 + nt*8;
            *(uint32_t*)&dsth[(size_t)row*DIM + col] =
                pack2h(__float2half(acc[mt][nt][0]), __float2half(acc[mt][nt][1]));
            *(uint32_t*)&dsth[(size_t)(row+8)*DIM + col] =
                pack2h(__float2half(acc[mt][nt][2]), __float2half(acc[mt][nt][3]));
            if (isq) {
                *(float2*)&dq[(size_t)row*DIM + col]     = make_float2(acc[mt][nt][0], acc[mt][nt][1]);
                *(float2*)&dq[(size_t)(row+8)*DIM + col] = make_float2(acc[mt][nt][2], acc[mt][nt][3]);
            }
        }
}

// ---------------- K2: uv + bilinear (fp16 gathers) + attention + residual + LN1 ----------------
__global__ void __launch_bounds__(256) k_attn(const float* __restrict__ ln1g,
                                              const float* __restrict__ ln1b) {
    __shared__ float sHm[BNV*9];
    int t = threadIdx.x;
    if (t < BNV*9) sHm[t] = g_Hm[t];
    __syncthreads();

    int warp = t >> 5, lane = t & 31;
    int pix = blockIdx.x * 8 + warp;
    int b = pix / P_;
    int p = pix - b * P_;
    int x = p % W_, y = p / W_;
    float px = ((float)x / (float)(W_-1)) * IMG_W_;
    float py = ((float)y / (float)(H_-1)) * IMG_H_;
    int d0 = lane << 2;

    const float4 q4 = *(const float4*)&g_q[((size_t)b*P_ + p) * DIM + d0];
    float qs = q4.x*q4.x + q4.y*q4.y + q4.z*q4.z + q4.w*q4.w;

    float vb[N_][4];
    float ssv[N_], ddv[N_], valid[N_];
    #pragma unroll
    for (int n = 0; n < N_; n++) {
        int bn = b*N_ + n;
        const float* Hm = &sHm[bn*9];
        float hx = Hm[0]*px + Hm[1]*py + Hm[2];
        float hy = Hm[3]*px + Hm[4]*py + Hm[5];
        float hz = Hm[6]*px + Hm[7]*py + Hm[8];
        float ux = ((hx / hz) / IMG_W_) * (float)W_;
        float uy = ((hy / hz) / IMG_H_) * (float)H_;
        float fx = floorf(ux), fy = floorf(uy);
        float wx = ux - fx,  wy = uy - fy;
        valid[n] = (ux >= 0.f && ux <= (float)(W_-1) &&
                    uy >= 0.f && uy <= (float)(H_-1)) ? 1.0f : 0.0f;
        int x0 = min(max((int)fx, 0), W_-1);
        int x1 = min(x0+1, W_-1);
        int y0 = min(max((int)fy, 0), H_-1);
        int y1 = min(y0+1, H_-1);
        float w00 = (1.f-wx)*(1.f-wy), w01 = wx*(1.f-wy);
        float w10 = (1.f-wx)*wy,       w11 = wx*wy;
        const __half* baseh = g_valh + (size_t)bn*P_*DIM + d0;
        uint2 u00 = *(const uint2*)&baseh[(size_t)(y0*W_+x0)*DIM];
        uint2 u01 = *(const uint2*)&baseh[(size_t)(y0*W_+x1)*DIM];
        uint2 u10 = *(const uint2*)&baseh[(size_t)(y1*W_+x0)*DIM];
        uint2 u11 = *(const uint2*)&baseh[(size_t)(y1*W_+x1)*DIM];
        float2 a00a = __half22float2(*(__half2*)&u00.x), a00b = __half22float2(*(__half2*)&u00.y);
        float2 a01a = __half22float2(*(__half2*)&u01.x), a01b = __half22float2(*(__half2*)&u01.y);
        float2 a10a = __half22float2(*(__half2*)&u10.x), a10b = __half22float2(*(__half2*)&u10.y);
        float2 a11a = __half22float2(*(__half2*)&u11.x), a11b = __half22float2(*(__half2*)&u11.y);
        float v0 = a00a.x*w00 + a01a.x*w01 + a10a.x*w10 + a11a.x*w11;
        float v1 = a00a.y*w00 + a01a.y*w01 + a10a.y*w10 + a11a.y*w11;
        float v2 = a00b.x*w00 + a01b.x*w01 + a10b.x*w10 + a11b.x*w11;
        float v3 = a00b.y*w00 + a01b.y*w01 + a10b.y*w10 + a11b.y*w11;
        vb[n][0] = v0; vb[n][1] = v1; vb[n][2] = v2; vb[n][3] = v3;
        ssv[n] = v0*v0 + v1*v1 + v2*v2 + v3*v3;
        ddv[n] = q4.x*v0 + q4.y*v1 + q4.z*v2 + q4.w*v3;
    }
    qs = wsum(qs);
    #pragma unroll
    for (int n = 0; n < N_; n++) { ssv[n] = wsum(ssv[n]); ddv[n] = wsum(ddv[n]); }
    float qinv = 1.0f / fmaxf(sqrtf(qs), 1e-12f);
    float dot[N_];
    #pragma unroll
    for (int n = 0; n < N_; n++)
        dot[n] = ddv[n] * qinv * (1.0f / fmaxf(sqrtf(ssv[n]), 1e-12f)) * valid[n];

    float m = dot[0];
    #pragma unroll
    for (int n = 1; n < N_; n++) m = fmaxf(m, dot[n]);
    float e[N_], s = 0.f;
    #pragma unroll
    for (int n = 0; n < N_; n++) { e[n] = expf(dot[n] - m); s += e[n]; }
    float sinv = 1.0f / s;
    float z[4] = {q4.x, q4.y, q4.z, q4.w};
    #pragma unroll
    for (int n = 0; n < N_; n++) {
        float a = e[n] * sinv;
        #pragma unroll
        for (int i = 0; i < 4; i++) z[i] = fmaf(a, vb[n][i], z[i]);
    }
    float ls = z[0] + z[1] + z[2] + z[3];
    ls = wsum(ls);
    float mean = ls * (1.0f / DIM);
    float vv = 0.f;
    #pragma unroll
    for (int i = 0; i < 4; i++) { float d = z[i] - mean; vv += d*d; }
    vv = wsum(vv);
    float rstd = 1.0f / sqrtf(vv * (1.0f / DIM) + 1e-5f);
    float4 g4 = *(const float4*)&ln1g[d0];
    float4 b4 = *(const float4*)&ln1b[d0];
    float zn[4];
    zn[0] = (z[0]-mean)*rstd*g4.x + b4.x;
    zn[1] = (z[1]-mean)*rstd*g4.y + b4.y;
    zn[2] = (z[2]-mean)*rstd*g4.z + b4.z;
    zn[3] = (z[3]-mean)*rstd*g4.w + b4.w;
    *(float4*)&g_zln[(size_t)pix*DIM + d0] = make_float4(zn[0], zn[1], zn[2], zn[3]);
    *(uint2*)&g_zh[(size_t)pix*DIM + d0] =
        make_uint2(pack2h(__float2half(zn[0]), __float2half(zn[1])),
                   pack2h(__float2half(zn[2]), __float2half(zn[3])));
}

// ---------------- K3: MLP1 (CTA 128tok x 64j, 3 CTAs/SM) ----------------
__global__ void __launch_bounds__(256, 3) k_mlp1_tc(const float* __restrict__ b1) {
    extern __shared__ __half smh[];
    __half* sA  = smh;                  // 128 x 72
    __half* sBh = smh + 128*TPAD72;     // 64 x 72
    __half* sBl = sBh + 64*TPAD72;      // 64 x 72
    int t = threadIdx.x, wid = t >> 5, lane = t & 31;
    int t0 = blockIdx.x * 128;
    int j0 = blockIdx.y * 64;

    float acc[2][4][4] = {};
    int wm = (wid >> 1) * 32;
    int wn = (wid & 1) * 32;
    const __half* Ag = g_zh + (size_t)t0 * DIM;
    const __half* Bh = g_w1h + (size_t)j0 * DIM;
    const __half* Bl = g_w1l + (size_t)j0 * DIM;

    #pragma unroll 1
    for (int c = 0; c < 2; c++) {
        if (c) __syncthreads();
        int c0 = c * 64;
        load_rows72(Ag, DIM, c0, sA, 128, t);
        load_rows72(Bh, DIM, c0, sBh, 64, t);
        load_rows72(Bl, DIM, c0, sBl, 64, t);
        cpa_commit();
        cpa_wait0();
        __syncthreads();
        gemm64_w32(acc, sA, sBh, sBl, wm, wn, lane);
    }

    int r0 = wm + (lane >> 2);
    int c0 = wn + (lane & 3) * 2;
    #pragma unroll
    for (int mt = 0; mt < 2; mt++)
        #pragma unroll
        for (int nt = 0; nt < 4; nt++) {
            int row = r0 + mt*16, col = c0 + nt*8;
            float bj0 = b1[j0 + col], bj1 = b1[j0 + col + 1];
            float v00 = gelu_exact(acc[mt][nt][0] + bj0);
            float v01 = gelu_exact(acc[mt][nt][1] + bj1);
            float v10 = gelu_exact(acc[mt][nt][2] + bj0);
            float v11 = gelu_exact(acc[mt][nt][3] + bj1);
            *(uint32_t*)&g_hh[(size_t)(t0+row)*(2*DIM) + j0 + col] =
                pack2h(__float2half(v00), __float2half(v01));
            *(uint32_t*)&g_hh[(size_t)(t0+row+8)*(2*DIM) + j0 + col] =
                pack2h(__float2half(v10), __float2half(v11));
        }
}

// ---------------- K4: MLP2 (CTA 64tok x 128d, 3 CTAs/SM) + residual + LN2 ----------------
__global__ void __launch_bounds__(256, 3) k_mlp2_tc(const float* __restrict__ b2,
                                                    const float* __restrict__ g2,
                                                    const float* __restrict__ bb2,
                                                    float* __restrict__ out) {
    extern __shared__ __half smh[];
    __half* sA  = smh;                  // 64 x 72
    __half* sBh = smh + 64*TPAD72;      // 128 x 72
    __half* sBl = sBh + 128*TPAD72;     // 128 x 72
    int t = threadIdx.x, wid = t >> 5, lane = t & 31;
    int t0 = blockIdx.x * 64;

    float acc[2][4][4] = {};
    int wm = (wid >> 2) * 32;
    int wn = (wid & 3) * 32;
    const __half* Ag = g_hh + (size_t)t0 * (2*DIM);

    #pragma unroll 1
    for (int c = 0; c < 4; c++) {
        if (c) __syncthreads();
        int c0 = c * 64;
        load_rows72(Ag,    2*DIM, c0, sA,   64, t);
        load_rows72(g_w2h, 2*DIM, c0, sBh, 128, t);
        load_rows72(g_w2l, 2*DIM, c0, sBl, 128, t);
        cpa_commit();
        cpa_wait0();
        __syncthreads();
        gemm64_w32(acc, sA, sBh, sBl, wm, wn, lane);
    }
    __syncthreads();   // smem reuse

    float* smT   = (float*)smh;         // [64][129] fp32
    float* sMean = smT + 64*129;
    float* sRstd = sMean + 64;
    const float* zb = g_zln + (size_t)t0 * DIM;
    int r0 = wm + (lane >> 2);
    int c0 = wn + (lane & 3) * 2;
    #pragma unroll
    for (int mt = 0; mt < 2; mt++)
        #pragma unroll
        for (int nt = 0; nt < 4; nt++) {
            int row = r0 + mt*16, col = c0 + nt*8;
            float b20 = b2[col], b21 = b2[col+1];
            float2 z0 = *(const float2*)&zb[(size_t)row*DIM + col];
            float2 z1 = *(const float2*)&zb[(size_t)(row+8)*DIM + col];
            smT[row*129 + col]       = acc[mt][nt][0] + b20 + z0.x;
            smT[row*129 + col + 1]   = acc[mt][nt][1] + b21 + z0.y;
            smT[(row+8)*129 + col]   = acc[mt][nt][2] + b20 + z1.x;
            smT[(row+8)*129 + col+1] = acc[mt][nt][3] + b21 + z1.y;
        }
    __syncthreads();
    if (t < 64) {
        float s = 0.f, q = 0.f;
        #pragma unroll 8
        for (int c = 0; c < 128; c++) {
            float v = smT[t*129 + c];
            s += v; q += v*v;
        }
        float mean = s * (1.0f / DIM);
        float var  = fmaxf(q * (1.0f / DIM) - mean*mean, 0.0f);
        sMean[t] = mean;
        sRstd[t] = 1.0f / sqrtf(var + 1e-5f);
    }
    __syncthreads();
    int b = t0 / P_;
    int prem = t0 - b * P_;
    #pragma unroll 4
    for (int k = 0; k < 32; k++) {
        int idx = k * 256 + t;
        int d = idx >> 6, p = idx & 63;   // consecutive t -> consecutive p
        float v = smT[p*129 + d];
        out[((size_t)(b*DIM + d))*P_ + prem + p] =
            (v - sMean[p]) * sRstd[p] * g2[d] + bb2[d];
    }
}

// ---------------- launch ----------------
extern "C" void kernel_launch(void* const* d_in, const int* in_sizes, int n_in,
                              void* d_out, int out_size) {
    const float* feature   = (const float*)d_in[0];
    const float* I_src     = (const float*)d_in[1];
    const float* I_tar_inv = (const float*)d_in[2];
    const float* E         = (const float*)d_in[3];
    const float* dis       = (const float*)d_in[4];
    const float* nrm       = (const float*)d_in[5];
    const float* conv_w    = (const float*)d_in[6];
    const float* bn_gamma  = (const float*)d_in[7];
    const float* bn_beta   = (const float*)d_in[8];
    const float* bn_mean   = (const float*)d_in[9];
    const float* bn_var    = (const float*)d_in[10];
    const float* ln1_g     = (const float*)d_in[11];
    const float* ln1_b     = (const float*)d_in[12];
    const float* ln2_g     = (const float*)d_in[13];
    const float* ln2_b     = (const float*)d_in[14];
    const float* mlp_w1    = (const float*)d_in[15];
    const float* mlp_b1    = (const float*)d_in[16];
    const float* mlp_w2    = (const float*)d_in[17];
    const float* mlp_b2    = (const float*)d_in[18];
    float* out = (float*)d_out;

    cudaFuncSetAttribute(k_conv_tc, cudaFuncAttributeMaxDynamicSharedMemorySize, SMEM_CONV);
    cudaFuncSetAttribute(k_mlp1_tc, cudaFuncAttributeMaxDynamicSharedMemorySize, SMEM_MLP1);
    cudaFuncSetAttribute(k_mlp2_tc, cudaFuncAttributeMaxDynamicSharedMemorySize, SMEM_MLP2);

    k_setup<<<48, 256>>>(I_src, I_tar_inv, E, dis, nrm, conv_w,
                         bn_gamma, bn_beta, bn_mean, bn_var, mlp_w1, mlp_w2);
    k_conv_tc<<<dim3(P_/128, BNV), 256, SMEM_CONV>>>(feature);
    k_attn<<<T2/8, 256>>>(ln1_g, ln1_b);
    k_mlp1_tc<<<dim3(T2/128, 4), 256, SMEM_MLP1>>>(mlp_b1);
    k_mlp2_tc<<<T2/64, 256, SMEM_MLP2>>>(mlp_b2, ln2_g, ln2_b, out);
}

// round 13
// speedup vs baseline: 1.5920x; 1.5029x over previous
#include <cuda_runtime.h>
#include <cuda_fp16.h>
#include <math.h>
#include <stdint.h>

#define B_    2
#define N_    6
#define FD    128
#define DIM   128
#define H_    64
#define W_    176
#define P_    (H_*W_)          // 11264
#define BNV   (B_*N_)          // 12
#define T2    (B_*P_)          // 22528
#define IMG_W_ 704.0f
#define IMG_H_ 256.0f

// conv chunk tiles: 128 x 32 fp16, padded to 40 (80 B rows)
#define TPAD40   40
#define TROWB40  80
#define PLANE40  (128*TPAD40)
#define SMEM_CONV (2*2*PLANE40*2)            // 2 stages x (A,Bh) = 40960 B
// mlp tiles: rows x 64 fp16, padded to 72 (144 B rows)
#define TPAD72   72
#define TROWB72  144
#define SMEM_MLP1 ((128+64)*TPAD72*2)        // 27648 B
#define SMEM_MLP2 ((64+128+128)*TPAD72*2)    // 46080 B

// ---------------- scratch ----------------
__device__ float  g_Hm[BNV*9];
__device__ float  g_bns[FD];
__device__ float  g_bnt[FD];
__device__ __half g_wch[DIM*FD];                           // conv W [o][c] fp16
__device__ __half g_w1h[(2*DIM)*DIM];                      // w1^T [j][c] fp16
__device__ __half g_w2h[DIM*(2*DIM)], g_w2l[DIM*(2*DIM)];  // w2^T [d][j] split
__device__ __half g_valh[(size_t)BNV*P_*DIM];              // conv out fp16 (gathers)
__device__ float  g_q[(size_t)B_*P_*DIM];                  // conv out fp32, n=0 (query)
__device__ float  g_zln[(size_t)T2*DIM];                   // post-LN1 fp32 (residual)
__device__ __half g_zh[(size_t)T2*DIM];                    // post-LN1 fp16 (mlp1 A)
__device__ __half g_hh[(size_t)T2*(2*DIM)];                // hidden fp16 (mlp2 A)

// ---------------- helpers ----------------
__device__ __forceinline__ float wsum(float v) {
    #pragma unroll
    for (int o = 16; o > 0; o >>= 1) v += __shfl_xor_sync(0xFFFFFFFFu, v, o);
    return v;
}
__device__ __forceinline__ float gelu_exact(float x) {
    return 0.5f * x * (1.0f + erff(x * 0.70710678118654752f));
}
__device__ __forceinline__ uint32_t pack2h(__half a, __half b) {
    return (uint32_t)__half_as_ushort(a) | ((uint32_t)__half_as_ushort(b) << 16);
}

// ---------------- async copy ----------------
__device__ __forceinline__ void cpa16(uint32_t s, const void* g) {
    asm volatile("cp.async.cg.shared.global [%0], [%1], 16;" :: "r"(s), "l"(g));
}
__device__ __forceinline__ void cpa_commit() { asm volatile("cp.async.commit_group;"); }
__device__ __forceinline__ void cpa_wait0()  { asm volatile("cp.async.wait_group 0;"); }

// rows x 64 fp16 chunk of a row-major plane -> 144B-stride smem tile
__device__ __forceinline__ void load_rows72(const __half* g, int rstride, int c0,
                                            __half* sm, int rows, int t) {
    uint32_t sb = (uint32_t)__cvta_generic_to_shared(sm);
    for (int i = t; i < rows*8; i += 256) {
        int row = i >> 3, seg = i & 7;
        cpa16(sb + row*TROWB72 + seg*16, g + (size_t)row*rstride + c0 + seg*8);
    }
}
// 128 x 32 fp16 chunk -> 80B-stride smem tile (2 cp.async/thread)
__device__ __forceinline__ void load_rows40(const __half* g, int rstride, int c0,
                                            __half* sm, int t) {
    uint32_t sb = (uint32_t)__cvta_generic_to_shared(sm);
    #pragma unroll
    for (int k = 0; k < 2; k++) {
        int i = k*256 + t;
        int row = i >> 2, seg = i & 3;
        cpa16(sb + row*TROWB40 + seg*16, g + (size_t)row*rstride + c0 + seg*8);
    }
}

// ---------------- warp-mma primitives ----------------
__device__ __forceinline__ void ldsm4(uint32_t* r, uint32_t addr) {
    asm volatile("ldmatrix.sync.aligned.m8n8.x4.shared.b16 {%0,%1,%2,%3}, [%4];"
        : "=r"(r[0]), "=r"(r[1]), "=r"(r[2]), "=r"(r[3]) : "r"(addr));
}
__device__ __forceinline__ void ldsm2(uint32_t* r, uint32_t addr) {
    asm volatile("ldmatrix.sync.aligned.m8n8.x2.shared.b16 {%0,%1}, [%2];"
        : "=r"(r[0]), "=r"(r[1]) : "r"(addr));
}
__device__ __forceinline__ void mma_f16(float* d, const uint32_t* a, const uint32_t* b) {
    asm volatile("mma.sync.aligned.m16n8k16.row.col.f32.f16.f16.f32 "
        "{%0,%1,%2,%3}, {%4,%5,%6,%7}, {%8,%9}, {%0,%1,%2,%3};"
        : "+f"(d[0]), "+f"(d[1]), "+f"(d[2]), "+f"(d[3])
        : "r"(a[0]), "r"(a[1]), "r"(a[2]), "r"(a[3]), "r"(b[0]), "r"(b[1]));
}

// K=32 chunk, warp tile 64x32 (conv): acc += A*Bh^T (single B plane)
__device__ __forceinline__ void gemm32_w64_1(float acc[4][4][4],
                                             const __half* sA, const __half* sBh,
                                             int wm, int wn, int lane) {
    uint32_t aB = (uint32_t)__cvta_generic_to_shared(sA);
    uint32_t bH = (uint32_t)__cvta_generic_to_shared(sBh);
    uint32_t aoff = (uint32_t)(wm + (lane & 15)) * TROWB40 + ((lane >> 4) << 4);
    uint32_t boff = (uint32_t)(wn + (lane & 7))  * TROWB40 + (((lane >> 3) & 1) << 4);
    #pragma unroll
    for (int kk = 0; kk < 2; kk++) {
        uint32_t kb = (uint32_t)kk * 32;
        uint32_t ah[4][4], bh[4][2];
        #pragma unroll
        for (int mt = 0; mt < 4; mt++)
            ldsm4(ah[mt], aB + aoff + (uint32_t)mt*16*TROWB40 + kb);
        #pragma unroll
        for (int nt = 0; nt < 4; nt++)
            ldsm2(bh[nt], bH + boff + (uint32_t)nt*8*TROWB40 + kb);
        #pragma unroll
        for (int mt = 0; mt < 4; mt++)
            #pragma unroll
            for (int nt = 0; nt < 4; nt++)
                mma_f16(acc[mt][nt], ah[mt], bh[nt]);
    }
}

// K=64 chunk, warp tile 32x32, single B plane (mlp1)
__device__ __forceinline__ void gemm64_w32_1(float acc[2][4][4],
                                             const __half* sA, const __half* sBh,
                                             int wm, int wn, int lane) {
    uint32_t aB = (uint32_t)__cvta_generic_to_shared(sA);
    uint32_t bH = (uint32_t)__cvta_generic_to_shared(sBh);
    uint32_t aoff = (uint32_t)(wm + (lane & 15)) * TROWB72 + ((lane >> 4) << 4);
    uint32_t boff = (uint32_t)(wn + (lane & 7))  * TROWB72 + (((lane >> 3) & 1) << 4);
    #pragma unroll
    for (int kk = 0; kk < 4; kk++) {
        uint32_t kb = (uint32_t)kk * 32;
        uint32_t ah[2][4], bh[4][2];
        #pragma unroll
        for (int mt = 0; mt < 2; mt++)
            ldsm4(ah[mt], aB + aoff + (uint32_t)mt*16*TROWB72 + kb);
        #pragma unroll
        for (int nt = 0; nt < 4; nt++)
            ldsm2(bh[nt], bH + boff + (uint32_t)nt*8*TROWB72 + kb);
        #pragma unroll
        for (int mt = 0; mt < 2; mt++)
            #pragma unroll
            for (int nt = 0; nt < 4; nt++)
                mma_f16(acc[mt][nt], ah[mt], bh[nt]);
    }
}

// K=64 chunk, warp tile 32x32, split B (mlp2)
__device__ __forceinline__ void gemm64_w32(float acc[2][4][4],
                                           const __half* sA, const __half* sBh,
                                           const __half* sBl, int wm, int wn, int lane) {
    uint32_t aB = (uint32_t)__cvta_generic_to_shared(sA);
    uint32_t bH = (uint32_t)__cvta_generic_to_shared(sBh);
    uint32_t bL = (uint32_t)__cvta_generic_to_shared(sBl);
    uint32_t aoff = (uint32_t)(wm + (lane & 15)) * TROWB72 + ((lane >> 4) << 4);
    uint32_t boff = (uint32_t)(wn + (lane & 7))  * TROWB72 + (((lane >> 3) & 1) << 4);
    #pragma unroll
    for (int kk = 0; kk < 4; kk++) {
        uint32_t kb = (uint32_t)kk * 32;
        uint32_t ah[2][4], bh[4][2], bl[4][2];
        #pragma unroll
        for (int mt = 0; mt < 2; mt++)
            ldsm4(ah[mt], aB + aoff + (uint32_t)mt*16*TROWB72 + kb);
        #pragma unroll
        for (int nt = 0; nt < 4; nt++) {
            uint32_t o = boff + (uint32_t)nt*8*TROWB72 + kb;
            ldsm2(bh[nt], bH + o);
            ldsm2(bl[nt], bL + o);
        }
        #pragma unroll
        for (int mt = 0; mt < 2; mt++)
            #pragma unroll
            for (int nt = 0; nt < 4; nt++) {
                mma_f16(acc[mt][nt], ah[mt], bh[nt]);
                mma_f16(acc[mt][nt], ah[mt], bl[nt]);
            }
    }
}

// ---------------- K0: setup ----------------
__global__ void k_setup(const float* __restrict__ I_src, const float* __restrict__ I_tar_inv,
                        const float* __restrict__ E, const float* __restrict__ dis,
                        const float* __restrict__ nrm, const float* __restrict__ conv_w,
                        const float* __restrict__ bg, const float* __restrict__ bb,
                        const float* __restrict__ bm, const float* __restrict__ bv,
                        const float* __restrict__ w1, const float* __restrict__ w2) {
    int t = threadIdx.x;
    if (blockIdx.x == 0) {
        if (t < BNV) {
            int b = t / N_;
            float ds = dis[b];
            float M[9], A[9];
            #pragma unroll
            for (int i = 0; i < 3; i++) {
                float Ti = E[t*16 + i*4 + 3];
                #pragma unroll
                for (int j = 0; j < 3; j++)
                    M[i*3+j] = E[t*16 + i*4 + j] - Ti * nrm[b*3+j] / ds;
            }
            #pragma unroll
            for (int i = 0; i < 3; i++)
                #pragma unroll
                for (int j = 0; j < 3; j++) {
                    float s = 0.f;
                    #pragma unroll
                    for (int k = 0; k < 3; k++) s += I_src[t*9 + i*3 + k] * M[k*3+j];
                    A[i*3+j] = s;
                }
            #pragma unroll
            for (int i = 0; i < 3; i++)
                #pragma unroll
                for (int j = 0; j < 3; j++) {
                    float s = 0.f;
                    #pragma unroll
                    for (int k = 0; k < 3; k++) s += A[i*3+k] * I_tar_inv[b*9 + k*3 + j];
                    g_Hm[t*9 + i*3 + j] = s;
                }
        }
        if (t < FD) {
            float s = bg[t] / sqrtf(bv[t] + 1e-5f);
            g_bns[t] = s;
            g_bnt[t] = bb[t] - bm[t] * s;
        }
    }
    int g = blockIdx.x * blockDim.x + t;
    int stride = gridDim.x * blockDim.x;
    for (int i = g; i < DIM*FD; i += stride)
        g_wch[i] = __float2half(conv_w[i]);
    for (int i = g; i < (2*DIM)*DIM; i += stride) {
        int j = i >> 7, c = i & 127;
        g_w1h[i] = __float2half(w1[c*(2*DIM) + j]);
    }
    for (int i = g; i < DIM*(2*DIM); i += stride) {
        int d = i >> 8, j = i & 255;
        float w = w2[j*DIM + d];
        __half h = __float2half(w);
        g_w2h[i] = h;
        g_w2l[i] = __float2half(w - __half2float(h));
    }
}

// ---------------- K1: conv GEMM (CTA 128p x 128o, single-B, pipelined) ----------------
__global__ void __launch_bounds__(256, 2) k_conv_tc(const float* __restrict__ feat) {
    extern __shared__ __half smh[];
    __half* stage[2] = { smh, smh + 2*PLANE40 };
    int t = threadIdx.x, wid = t >> 5, lane = t & 31;
    int bn = blockIdx.y;
    int p0 = blockIdx.x * 128;

    float acc[4][4][4] = {};
    int wm = (wid >> 2) * 64, wn = (wid & 3) * 32;
    const float* fb = feat + (size_t)bn * FD * P_ + p0;
    int ap  = t & 127;               // pixel
    int acb = (t >> 7) * 16;         // 16-channel base within chunk

    float rA[16];
    #pragma unroll
    for (int k = 0; k < 16; k++) {
        int c = acb + k;
        rA[k] = fmaxf(fmaf(fb[(size_t)c * P_ + ap], g_bns[c], g_bnt[c]), 0.f);
    }
    load_rows40(g_wch, FD, 0, stage[0] + PLANE40, t);
    cpa_commit();

    #pragma unroll 1
    for (int i = 0; i < 4; i++) {
        cpa_wait0();
        {
            __half* sA = stage[i & 1];
            #pragma unroll
            for (int j = 0; j < 8; j++)
                *(uint32_t*)&sA[ap*TPAD40 + acb + 2*j] =
                    pack2h(__float2half(rA[2*j]), __float2half(rA[2*j+1]));
        }
        if (i < 3) {
            int c0n = (i + 1) * 32;
            #pragma unroll
            for (int k = 0; k < 16; k++) {
                int c = c0n + acb + k;
                rA[k] = fmaxf(fmaf(fb[(size_t)c * P_ + ap], g_bns[c], g_bnt[c]), 0.f);
            }
        }
        __syncthreads();
        if (i < 3) {
            int c0n = (i + 1) * 32;
            load_rows40(g_wch, FD, c0n, stage[(i+1) & 1] + PLANE40, t);
            cpa_commit();
        }
        gemm32_w64_1(acc, stage[i & 1], stage[i & 1] + PLANE40, wm, wn, lane);
    }

    __half* dsth = g_valh + ((size_t)bn * P_ + p0) * DIM;
    int r0 = wm + (lane >> 2);
    int c0 = wn + (lane & 3) * 2;
    bool isq = (bn % N_) == 0;
    float* dq = g_q + ((size_t)(bn / N_) * P_ + p0) * DIM;
    #pragma unroll
    for (int mt = 0; mt < 4; mt++)
        #pragma unroll
        for (int nt = 0; nt < 4; nt++) {
            int row = r0 + mt*16, col = c0 + nt*8;
            *(uint32_t*)&dsth[(size_t)row*DIM + col] =
                pack2h(__float2half(acc[mt][nt][0]), __float2half(acc[mt][nt][1]));
            *(uint32_t*)&dsth[(size_t)(row+8)*DIM + col] =
                pack2h(__float2half(acc[mt][nt][2]), __float2half(acc[mt][nt][3]));
            if (isq) {
                *(float2*)&dq[(size_t)row*DIM + col]     = make_float2(acc[mt][nt][0], acc[mt][nt][1]);
                *(float2*)&dq[(size_t)(row+8)*DIM + col] = make_float2(acc[mt][nt][2], acc[mt][nt][3]);
            }
        }
}

// ---------------- K2: uv + bilinear (fp16 gathers) + attention + residual + LN1 ----------------
__global__ void __launch_bounds__(256) k_attn(const float* __restrict__ ln1g,
                                              const float* __restrict__ ln1b) {
    __shared__ float sHm[BNV*9];
    int t = threadIdx.x;
    if (t < BNV*9) sHm[t] = g_Hm[t];
    __syncthreads();

    int warp = t >> 5, lane = t & 31;
    int pix = blockIdx.x * 8 + warp;
    int b = pix / P_;
    int p = pix - b * P_;
    int x = p % W_, y = p / W_;
    float px = ((float)x / (float)(W_-1)) * IMG_W_;
    float py = ((float)y / (float)(H_-1)) * IMG_H_;
    int d0 = lane << 2;

    const float4 q4 = *(const float4*)&g_q[((size_t)b*P_ + p) * DIM + d0];
    float qs = q4.x*q4.x + q4.y*q4.y + q4.z*q4.z + q4.w*q4.w;

    float vb[N_][4];
    float ssv[N_], ddv[N_], valid[N_];
    #pragma unroll
    for (int n = 0; n < N_; n++) {
        int bn = b*N_ + n;
        const float* Hm = &sHm[bn*9];
        float hx = Hm[0]*px + Hm[1]*py + Hm[2];
        float hy = Hm[3]*px + Hm[4]*py + Hm[5];
        float hz = Hm[6]*px + Hm[7]*py + Hm[8];
        float ux = ((hx / hz) / IMG_W_) * (float)W_;
        float uy = ((hy / hz) / IMG_H_) * (float)H_;
        float fx = floorf(ux), fy = floorf(uy);
        float wx = ux - fx,  wy = uy - fy;
        valid[n] = (ux >= 0.f && ux <= (float)(W_-1) &&
                    uy >= 0.f && uy <= (float)(H_-1)) ? 1.0f : 0.0f;
        int x0 = min(max((int)fx, 0), W_-1);
        int x1 = min(x0+1, W_-1);
        int y0 = min(max((int)fy, 0), H_-1);
        int y1 = min(y0+1, H_-1);
        float w00 = (1.f-wx)*(1.f-wy), w01 = wx*(1.f-wy);
        float w10 = (1.f-wx)*wy,       w11 = wx*wy;
        const __half* baseh = g_valh + (size_t)bn*P_*DIM + d0;
        uint2 u00 = *(const uint2*)&baseh[(size_t)(y0*W_+x0)*DIM];
        uint2 u01 = *(const uint2*)&baseh[(size_t)(y0*W_+x1)*DIM];
        uint2 u10 = *(const uint2*)&baseh[(size_t)(y1*W_+x0)*DIM];
        uint2 u11 = *(const uint2*)&baseh[(size_t)(y1*W_+x1)*DIM];
        float2 a00a = __half22float2(*(__half2*)&u00.x), a00b = __half22float2(*(__half2*)&u00.y);
        float2 a01a = __half22float2(*(__half2*)&u01.x), a01b = __half22float2(*(__half2*)&u01.y);
        float2 a10a = __half22float2(*(__half2*)&u10.x), a10b = __half22float2(*(__half2*)&u10.y);
        float2 a11a = __half22float2(*(__half2*)&u11.x), a11b = __half22float2(*(__half2*)&u11.y);
        float v0 = a00a.x*w00 + a01a.x*w01 + a10a.x*w10 + a11a.x*w11;
        float v1 = a00a.y*w00 + a01a.y*w01 + a10a.y*w10 + a11a.y*w11;
        float v2 = a00b.x*w00 + a01b.x*w01 + a10b.x*w10 + a11b.x*w11;
        float v3 = a00b.y*w00 + a01b.y*w01 + a10b.y*w10 + a11b.y*w11;
        vb[n][0] = v0; vb[n][1] = v1; vb[n][2] = v2; vb[n][3] = v3;
        ssv[n] = v0*v0 + v1*v1 + v2*v2 + v3*v3;
        ddv[n] = q4.x*v0 + q4.y*v1 + q4.z*v2 + q4.w*v3;
    }
    qs = wsum(qs);
    #pragma unroll
    for (int n = 0; n < N_; n++) { ssv[n] = wsum(ssv[n]); ddv[n] = wsum(ddv[n]); }
    float qinv = 1.0f / fmaxf(sqrtf(qs), 1e-12f);
    float dot[N_];
    #pragma unroll
    for (int n = 0; n < N_; n++)
        dot[n] = ddv[n] * qinv * (1.0f / fmaxf(sqrtf(ssv[n]), 1e-12f)) * valid[n];

    float m = dot[0];
    #pragma unroll
    for (int n = 1; n < N_; n++) m = fmaxf(m, dot[n]);
    float e[N_], s = 0.f;
    #pragma unroll
    for (int n = 0; n < N_; n++) { e[n] = expf(dot[n] - m); s += e[n]; }
    float sinv = 1.0f / s;
    float z[4] = {q4.x, q4.y, q4.z, q4.w};
    #pragma unroll
    for (int n = 0; n < N_; n++) {
        float a = e[n] * sinv;
        #pragma unroll
        for (int i = 0; i < 4; i++) z[i] = fmaf(a, vb[n][i], z[i]);
    }
    float ls = z[0] + z[1] + z[2] + z[3];
    ls = wsum(ls);
    float mean = ls * (1.0f / DIM);
    float vv = 0.f;
    #pragma unroll
    for (int i = 0; i < 4; i++) { float d = z[i] - mean; vv += d*d; }
    vv = wsum(vv);
    float rstd = 1.0f / sqrtf(vv * (1.0f / DIM) + 1e-5f);
    float4 g4 = *(const float4*)&ln1g[d0];
    float4 b4 = *(const float4*)&ln1b[d0];
    float zn[4];
    zn[0] = (z[0]-mean)*rstd*g4.x + b4.x;
    zn[1] = (z[1]-mean)*rstd*g4.y + b4.y;
    zn[2] = (z[2]-mean)*rstd*g4.z + b4.z;
    zn[3] = (z[3]-mean)*rstd*g4.w + b4.w;
    *(float4*)&g_zln[(size_t)pix*DIM + d0] = make_float4(zn[0], zn[1], zn[2], zn[3]);
    *(uint2*)&g_zh[(size_t)pix*DIM + d0] =
        make_uint2(pack2h(__float2half(zn[0]), __float2half(zn[1])),
                   pack2h(__float2half(zn[2]), __float2half(zn[3])));
}

// ---------------- K3: MLP1 (CTA 128tok x 64j, single-B, 3 CTAs/SM) ----------------
__global__ void __launch_bounds__(256, 3) k_mlp1_tc(const float* __restrict__ b1) {
    extern __shared__ __half smh[];
    __half* sA  = smh;                  // 128 x 72
    __half* sBh = smh + 128*TPAD72;     // 64 x 72
    int t = threadIdx.x, wid = t >> 5, lane = t & 31;
    int t0 = blockIdx.x * 128;
    int j0 = blockIdx.y * 64;

    float acc[2][4][4] = {};
    int wm = (wid >> 1) * 32;
    int wn = (wid & 1) * 32;
    const __half* Ag = g_zh + (size_t)t0 * DIM;
    const __half* Bh = g_w1h + (size_t)j0 * DIM;

    #pragma unroll 1
    for (int c = 0; c < 2; c++) {
        if (c) __syncthreads();
        int c0 = c * 64;
        load_rows72(Ag, DIM, c0, sA, 128, t);
        load_rows72(Bh, DIM, c0, sBh, 64, t);
        cpa_commit();
        cpa_wait0();
        __syncthreads();
        gemm64_w32_1(acc, sA, sBh, wm, wn, lane);
    }

    int r0 = wm + (lane >> 2);
    int c0 = wn + (lane & 3) * 2;
    #pragma unroll
    for (int mt = 0; mt < 2; mt++)
        #pragma unroll
        for (int nt = 0; nt < 4; nt++) {
            int row = r0 + mt*16, col = c0 + nt*8;
            float bj0 = b1[j0 + col], bj1 = b1[j0 + col + 1];
            float v00 = gelu_exact(acc[mt][nt][0] + bj0);
            float v01 = gelu_exact(acc[mt][nt][1] + bj1);
            float v10 = gelu_exact(acc[mt][nt][2] + bj0);
            float v11 = gelu_exact(acc[mt][nt][3] + bj1);
            *(uint32_t*)&g_hh[(size_t)(t0+row)*(2*DIM) + j0 + col] =
                pack2h(__float2half(v00), __float2half(v01));
            *(uint32_t*)&g_hh[(size_t)(t0+row+8)*(2*DIM) + j0 + col] =
                pack2h(__float2half(v10), __float2half(v11));
        }
}

// ---------------- K4: MLP2 (CTA 64tok x 128d, split-B, 3 CTAs/SM) + residual + LN2 ----------------
__global__ void __launch_bounds__(256, 3) k_mlp2_tc(const float* __restrict__ b2,
                                                    const float* __restrict__ g2,
                                                    const float* __restrict__ bb2,
                                                    float* __restrict__ out) {
    extern __shared__ __half smh[];
    __half* sA  = smh;                  // 64 x 72
    __half* sBh = smh + 64*TPAD72;      // 128 x 72
    __half* sBl = sBh + 128*TPAD72;     // 128 x 72
    int t = threadIdx.x, wid = t >> 5, lane = t & 31;
    int t0 = blockIdx.x * 64;

    float acc[2][4][4] = {};
    int wm = (wid >> 2) * 32;
    int wn = (wid & 3) * 32;
    const __half* Ag = g_hh + (size_t)t0 * (2*DIM);

    #pragma unroll 1
    for (int c = 0; c < 4; c++) {
        if (c) __syncthreads();
        int c0 = c * 64;
        load_rows72(Ag,    2*DIM, c0, sA,   64, t);
        load_rows72(g_w2h, 2*DIM, c0, sBh, 128, t);
        load_rows72(g_w2l, 2*DIM, c0, sBl, 128, t);
        cpa_commit();
        cpa_wait0();
        __syncthreads();
        gemm64_w32(acc, sA, sBh, sBl, wm, wn, lane);
    }
    __syncthreads();   // smem reuse

    float* smT   = (float*)smh;         // [64][129] fp32
    float* sMean = smT + 64*129;
    float* sRstd = sMean + 64;
    const float* zb = g_zln + (size_t)t0 * DIM;
    int r0 = wm + (lane >> 2);
    int c0 = wn + (lane & 3) * 2;
    #pragma unroll
    for (int mt = 0; mt < 2; mt++)
        #pragma unroll
        for (int nt = 0; nt < 4; nt++) {
            int row = r0 + mt*16, col = c0 + nt*8;
            float b20 = b2[col], b21 = b2[col+1];
            float2 z0 = *(const float2*)&zb[(size_t)row*DIM + col];
            float2 z1 = *(const float2*)&zb[(size_t)(row+8)*DIM + col];
            smT[row*129 + col]       = acc[mt][nt][0] + b20 + z0.x;
            smT[row*129 + col + 1]   = acc[mt][nt][1] + b21 + z0.y;
            smT[(row+8)*129 + col]   = acc[mt][nt][2] + b20 + z1.x;
            smT[(row+8)*129 + col+1] = acc[mt][nt][3] + b21 + z1.y;
        }
    __syncthreads();
    if (t < 64) {
        float s = 0.f, q = 0.f;
        #pragma unroll 8
        for (int c = 0; c < 128; c++) {
            float v = smT[t*129 + c];
            s += v; q += v*v;
        }
        float mean = s * (1.0f / DIM);
        float var  = fmaxf(q * (1.0f / DIM) - mean*mean, 0.0f);
        sMean[t] = mean;
        sRstd[t] = 1.0f / sqrtf(var + 1e-5f);
    }
    __syncthreads();
    int b = t0 / P_;
    int prem = t0 - b * P_;
    #pragma unroll 4
    for (int k = 0; k < 32; k++) {
        int idx = k * 256 + t;
        int d = idx >> 6, p = idx & 63;   // consecutive t -> consecutive p
        float v = smT[p*129 + d];
        out[((size_t)(b*DIM + d))*P_ + prem + p] =
            (v - sMean[p]) * sRstd[p] * g2[d] + bb2[d];
    }
}

// ---------------- launch ----------------
extern "C" void kernel_launch(void* const* d_in, const int* in_sizes, int n_in,
                              void* d_out, int out_size) {
    const float* feature   = (const float*)d_in[0];
    const float* I_src     = (const float*)d_in[1];
    const float* I_tar_inv = (const float*)d_in[2];
    const float* E         = (const float*)d_in[3];
    const float* dis       = (const float*)d_in[4];
    const float* nrm       = (const float*)d_in[5];
    const float* conv_w    = (const float*)d_in[6];
    const float* bn_gamma  = (const float*)d_in[7];
    const float* bn_beta   = (const float*)d_in[8];
    const float* bn_mean   = (const float*)d_in[9];
    const float* bn_var    = (const float*)d_in[10];
    const float* ln1_g     = (const float*)d_in[11];
    const float* ln1_b     = (const float*)d_in[12];
    const float* ln2_g     = (const float*)d_in[13];
    const float* ln2_b     = (const float*)d_in[14];
    const float* mlp_w1    = (const float*)d_in[15];
    const float* mlp_b1    = (const float*)d_in[16];
    const float* mlp_w2    = (const float*)d_in[17];
    const float* mlp_b2    = (const float*)d_in[18];
    float* out = (float*)d_out;

    cudaFuncSetAttribute(k_conv_tc, cudaFuncAttributeMaxDynamicSharedMemorySize, SMEM_CONV);
    cudaFuncSetAttribute(k_mlp1_tc, cudaFuncAttributeMaxDynamicSharedMemorySize, SMEM_MLP1);
    cudaFuncSetAttribute(k_mlp2_tc, cudaFuncAttributeMaxDynamicSharedMemorySize, SMEM_MLP2);

    k_setup<<<48, 256>>>(I_src, I_tar_inv, E, dis, nrm, conv_w,
                         bn_gamma, bn_beta, bn_mean, bn_var, mlp_w1, mlp_w2);
    k_conv_tc<<<dim3(P_/128, BNV), 256, SMEM_CONV>>>(feature);
    k_attn<<<T2/8, 256>>>(ln1_g, ln1_b);
    k_mlp1_tc<<<dim3(T2/128, 4), 256, SMEM_MLP1>>>(mlp_b1);
    k_mlp2_tc<<<T2/64, 256, SMEM_MLP2>>>(mlp_b2, ln2_g, ln2_b, out);
}

// round 15
// speedup vs baseline: 1.6893x; 1.0611x over previous
#include <cuda_runtime.h>
#include <cuda_fp16.h>
#include <math.h>
#include <stdint.h>

#define B_    2
#define N_    6
#define FD    128
#define DIM   128
#define H_    64
#define W_    176
#define P_    (H_*W_)          // 11264
#define BNV   (B_*N_)          // 12
#define T2    (B_*P_)          // 22528
#define IMG_W_ 704.0f
#define IMG_H_ 256.0f

// conv chunk tiles: 128 x 32 fp16, padded to 40 (80 B rows)
#define TPAD40   40
#define TROWB40  80
#define PLANE40  (128*TPAD40)
#define SMEM_CONV (2*2*PLANE40*2)            // 2 stages x (A,Bh) = 40960 B
// mlp tiles: rows x 64 fp16, padded to 72 (144 B rows)
#define TPAD72   72
#define TROWB72  144
#define SMEM_MLP1 ((128+64)*TPAD72*2)        // 27648 B
#define SMEM_MLP2 33792                      // gemm needs 27648; epilogue needs 33536

// ---------------- scratch ----------------
__device__ float  g_Hm[BNV*9];
__device__ float  g_bns[FD];
__device__ float  g_bnt[FD];
__device__ __half g_wch[DIM*FD];                           // conv W [o][c] fp16
__device__ __half g_w1h[(2*DIM)*DIM];                      // w1^T [j][c] fp16
__device__ __half g_w2h[DIM*(2*DIM)];                      // w2^T [d][j] fp16
__device__ __half g_valh[(size_t)BNV*P_*DIM];              // conv out fp16 (gathers)
__device__ float  g_q[(size_t)B_*P_*DIM];                  // conv out fp32, n=0 (query)
__device__ float  g_zln[(size_t)T2*DIM];                   // post-LN1 fp32 (residual)
__device__ __half g_zh[(size_t)T2*DIM];                    // post-LN1 fp16 (mlp1 A)
__device__ __half g_hh[(size_t)T2*(2*DIM)];                // hidden fp16 (mlp2 A)

// ---------------- helpers ----------------
__device__ __forceinline__ float wsum(float v) {
    #pragma unroll
    for (int o = 16; o > 0; o >>= 1) v += __shfl_xor_sync(0xFFFFFFFFu, v, o);
    return v;
}
__device__ __forceinline__ float gelu_exact(float x) {
    return 0.5f * x * (1.0f + erff(x * 0.70710678118654752f));
}
__device__ __forceinline__ uint32_t pack2h(__half a, __half b) {
    return (uint32_t)__half_as_ushort(a) | ((uint32_t)__half_as_ushort(b) << 16);
}

// ---------------- async copy ----------------
__device__ __forceinline__ void cpa16(uint32_t s, const void* g) {
    asm volatile("cp.async.cg.shared.global [%0], [%1], 16;" :: "r"(s), "l"(g));
}
__device__ __forceinline__ void cpa_commit() { asm volatile("cp.async.commit_group;"); }
__device__ __forceinline__ void cpa_wait0()  { asm volatile("cp.async.wait_group 0;"); }

// rows x 64 fp16 chunk of a row-major plane -> 144B-stride smem tile
__device__ __forceinline__ void load_rows72(const __half* g, int rstride, int c0,
                                            __half* sm, int rows, int t) {
    uint32_t sb = (uint32_t)__cvta_generic_to_shared(sm);
    for (int i = t; i < rows*8; i += 256) {
        int row = i >> 3, seg = i & 7;
        cpa16(sb + row*TROWB72 + seg*16, g + (size_t)row*rstride + c0 + seg*8);
    }
}
// 128 x 32 fp16 chunk -> 80B-stride smem tile (2 cp.async/thread)
__device__ __forceinline__ void load_rows40(const __half* g, int rstride, int c0,
                                            __half* sm, int t) {
    uint32_t sb = (uint32_t)__cvta_generic_to_shared(sm);
    #pragma unroll
    for (int k = 0; k < 2; k++) {
        int i = k*256 + t;
        int row = i >> 2, seg = i & 3;
        cpa16(sb + row*TROWB40 + seg*16, g + (size_t)row*rstride + c0 + seg*8);
    }
}

// ---------------- warp-mma primitives ----------------
__device__ __forceinline__ void ldsm4(uint32_t* r, uint32_t addr) {
    asm volatile("ldmatrix.sync.aligned.m8n8.x4.shared.b16 {%0,%1,%2,%3}, [%4];"
        : "=r"(r[0]), "=r"(r[1]), "=r"(r[2]), "=r"(r[3]) : "r"(addr));
}
__device__ __forceinline__ void ldsm2(uint32_t* r, uint32_t addr) {
    asm volatile("ldmatrix.sync.aligned.m8n8.x2.shared.b16 {%0,%1}, [%2];"
        : "=r"(r[0]), "=r"(r[1]) : "r"(addr));
}
__device__ __forceinline__ void mma_f16(float* d, const uint32_t* a, const uint32_t* b) {
    asm volatile("mma.sync.aligned.m16n8k16.row.col.f32.f16.f16.f32 "
        "{%0,%1,%2,%3}, {%4,%5,%6,%7}, {%8,%9}, {%0,%1,%2,%3};"
        : "+f"(d[0]), "+f"(d[1]), "+f"(d[2]), "+f"(d[3])
        : "r"(a[0]), "r"(a[1]), "r"(a[2]), "r"(a[3]), "r"(b[0]), "r"(b[1]));
}

// K=32 chunk, warp tile 64x32 (conv): acc += A*Bh^T
__device__ __forceinline__ void gemm32_w64_1(float acc[4][4][4],
                                             const __half* sA, const __half* sBh,
                                             int wm, int wn, int lane) {
    uint32_t aB = (uint32_t)__cvta_generic_to_shared(sA);
    uint32_t bH = (uint32_t)__cvta_generic_to_shared(sBh);
    uint32_t aoff = (uint32_t)(wm + (lane & 15)) * TROWB40 + ((lane >> 4) << 4);
    uint32_t boff = (uint32_t)(wn + (lane & 7))  * TROWB40 + (((lane >> 3) & 1) << 4);
    #pragma unroll
    for (int kk = 0; kk < 2; kk++) {
        uint32_t kb = (uint32_t)kk * 32;
        uint32_t ah[4][4], bh[4][2];
        #pragma unroll
        for (int mt = 0; mt < 4; mt++)
            ldsm4(ah[mt], aB + aoff + (uint32_t)mt*16*TROWB40 + kb);
        #pragma unroll
        for (int nt = 0; nt < 4; nt++)
            ldsm2(bh[nt], bH + boff + (uint32_t)nt*8*TROWB40 + kb);
        #pragma unroll
        for (int mt = 0; mt < 4; mt++)
            #pragma unroll
            for (int nt = 0; nt < 4; nt++)
                mma_f16(acc[mt][nt], ah[mt], bh[nt]);
    }
}

// K=64 chunk, warp tile 32x32, single B plane (mlp1/mlp2)
__device__ __forceinline__ void gemm64_w32_1(float acc[2][4][4],
                                             const __half* sA, const __half* sBh,
                                             int wm, int wn, int lane) {
    uint32_t aB = (uint32_t)__cvta_generic_to_shared(sA);
    uint32_t bH = (uint32_t)__cvta_generic_to_shared(sBh);
    uint32_t aoff = (uint32_t)(wm + (lane & 15)) * TROWB72 + ((lane >> 4) << 4);
    uint32_t boff = (uint32_t)(wn + (lane & 7))  * TROWB72 + (((lane >> 3) & 1) << 4);
    #pragma unroll
    for (int kk = 0; kk < 4; kk++) {
        uint32_t kb = (uint32_t)kk * 32;
        uint32_t ah[2][4], bh[4][2];
        #pragma unroll
        for (int mt = 0; mt < 2; mt++)
            ldsm4(ah[mt], aB + aoff + (uint32_t)mt*16*TROWB72 + kb);
        #pragma unroll
        for (int nt = 0; nt < 4; nt++)
            ldsm2(bh[nt], bH + boff + (uint32_t)nt*8*TROWB72 + kb);
        #pragma unroll
        for (int mt = 0; mt < 2; mt++)
            #pragma unroll
            for (int nt = 0; nt < 4; nt++)
                mma_f16(acc[mt][nt], ah[mt], bh[nt]);
    }
}

// ---------------- K0: setup ----------------
__global__ void k_setup(const float* __restrict__ I_src, const float* __restrict__ I_tar_inv,
                        const float* __restrict__ E, const float* __restrict__ dis,
                        const float* __restrict__ nrm, const float* __restrict__ conv_w,
                        const float* __restrict__ bg, const float* __restrict__ bb,
                        const float* __restrict__ bm, const float* __restrict__ bv,
                        const float* __restrict__ w1, const float* __restrict__ w2) {
    int t = threadIdx.x;
    if (blockIdx.x == 0) {
        if (t < BNV) {
            int b = t / N_;
            float ds = dis[b];
            float M[9], A[9];
            #pragma unroll
            for (int i = 0; i < 3; i++) {
                float Ti = E[t*16 + i*4 + 3];
                #pragma unroll
                for (int j = 0; j < 3; j++)
                    M[i*3+j] = E[t*16 + i*4 + j] - Ti * nrm[b*3+j] / ds;
            }
            #pragma unroll
            for (int i = 0; i < 3; i++)
                #pragma unroll
                for (int j = 0; j < 3; j++) {
                    float s = 0.f;
                    #pragma unroll
                    for (int k = 0; k < 3; k++) s += I_src[t*9 + i*3 + k] * M[k*3+j];
                    A[i*3+j] = s;
                }
            #pragma unroll
            for (int i = 0; i < 3; i++)
                #pragma unroll
                for (int j = 0; j < 3; j++) {
                    float s = 0.f;
                    #pragma unroll
                    for (int k = 0; k < 3; k++) s += A[i*3+k] * I_tar_inv[b*9 + k*3 + j];
                    g_Hm[t*9 + i*3 + j] = s;
                }
        }
        if (t < FD) {
            float s = bg[t] / sqrtf(bv[t] + 1e-5f);
            g_bns[t] = s;
            g_bnt[t] = bb[t] - bm[t] * s;
        }
    }
    int g = blockIdx.x * blockDim.x + t;
    int stride = gridDim.x * blockDim.x;
    for (int i = g; i < DIM*FD; i += stride)
        g_wch[i] = __float2half(conv_w[i]);
    for (int i = g; i < (2*DIM)*DIM; i += stride) {
        int j = i >> 7, c = i & 127;
        g_w1h[i] = __float2half(w1[c*(2*DIM) + j]);
    }
    for (int i = g; i < DIM*(2*DIM); i += stride) {
        int d = i >> 8, j = i & 255;
        g_w2h[i] = __float2half(w2[j*DIM + d]);
    }
}

// ---------------- K1: conv GEMM (CTA 128p x 128o, single-B, pipelined) ----------------
__global__ void __launch_bounds__(256, 2) k_conv_tc(const float* __restrict__ feat) {
    extern __shared__ __half smh[];
    __half* stage[2] = { smh, smh + 2*PLANE40 };
    int t = threadIdx.x, wid = t >> 5, lane = t & 31;
    int bn = blockIdx.y;
    int p0 = blockIdx.x * 128;

    float acc[4][4][4] = {};
    int wm = (wid >> 2) * 64, wn = (wid & 3) * 32;
    const float* fb = feat + (size_t)bn * FD * P_ + p0;
    int ap  = t & 127;               // pixel
    int acb = (t >> 7) * 16;         // 16-channel base within chunk

    float rA[16];
    #pragma unroll
    for (int k = 0; k < 16; k++) {
        int c = acb + k;
        rA[k] = fmaxf(fmaf(fb[(size_t)c * P_ + ap], g_bns[c], g_bnt[c]), 0.f);
    }
    load_rows40(g_wch, FD, 0, stage[0] + PLANE40, t);
    cpa_commit();

    #pragma unroll 1
    for (int i = 0; i < 4; i++) {
        cpa_wait0();
        {
            __half* sA = stage[i & 1];
            #pragma unroll
            for (int j = 0; j < 8; j++)
                *(uint32_t*)&sA[ap*TPAD40 + acb + 2*j] =
                    pack2h(__float2half(rA[2*j]), __float2half(rA[2*j+1]));
        }
        if (i < 3) {
            int c0n = (i + 1) * 32;
            #pragma unroll
            for (int k = 0; k < 16; k++) {
                int c = c0n + acb + k;
                rA[k] = fmaxf(fmaf(fb[(size_t)c * P_ + ap], g_bns[c], g_bnt[c]), 0.f);
            }
        }
        __syncthreads();
        if (i < 3) {
            int c0n = (i + 1) * 32;
            load_rows40(g_wch, FD, c0n, stage[(i+1) & 1] + PLANE40, t);
            cpa_commit();
        }
        gemm32_w64_1(acc, stage[i & 1], stage[i & 1] + PLANE40, wm, wn, lane);
    }

    __half* dsth = g_valh + ((size_t)bn * P_ + p0) * DIM;
    int r0 = wm + (lane >> 2);
    int c0 = wn + (lane & 3) * 2;
    bool isq = (bn % N_) == 0;
    float* dq = g_q + ((size_t)(bn / N_) * P_ + p0) * DIM;
    #pragma unroll
    for (int mt = 0; mt < 4; mt++)
        #pragma unroll
        for (int nt = 0; nt < 4; nt++) {
            int row = r0 + mt*16, col = c0 + nt*8;
            *(uint32_t*)&dsth[(size_t)row*DIM + col] =
                pack2h(__float2half(acc[mt][nt][0]), __float2half(acc[mt][nt][1]));
            *(uint32_t*)&dsth[(size_t)(row+8)*DIM + col] =
                pack2h(__float2half(acc[mt][nt][2]), __float2half(acc[mt][nt][3]));
            if (isq) {
                *(float2*)&dq[(size_t)row*DIM + col]     = make_float2(acc[mt][nt][0], acc[mt][nt][1]);
                *(float2*)&dq[(size_t)(row+8)*DIM + col] = make_float2(acc[mt][nt][2], acc[mt][nt][3]);
            }
        }
}

// ---------------- K2: uv + bilinear (fp16 gathers) + attention + residual + LN1 ----------------
__global__ void __launch_bounds__(256) k_attn(const float* __restrict__ ln1g,
                                              const float* __restrict__ ln1b) {
    __shared__ float sHm[BNV*9];
    int t = threadIdx.x;
    if (t < BNV*9) sHm[t] = g_Hm[t];
    __syncthreads();

    int warp = t >> 5, lane = t & 31;
    int pix = blockIdx.x * 8 + warp;
    int b = pix / P_;
    int p = pix - b * P_;
    int x = p % W_, y = p / W_;
    float px = ((float)x / (float)(W_-1)) * IMG_W_;
    float py = ((float)y / (float)(H_-1)) * IMG_H_;
    int d0 = lane << 2;

    const float4 q4 = *(const float4*)&g_q[((size_t)b*P_ + p) * DIM + d0];
    float qs = q4.x*q4.x + q4.y*q4.y + q4.z*q4.z + q4.w*q4.w;

    float vb[N_][4];
    float ssv[N_], ddv[N_], valid[N_];
    #pragma unroll
    for (int n = 0; n < N_; n++) {
        int bn = b*N_ + n;
        const float* Hm = &sHm[bn*9];
        float hx = Hm[0]*px + Hm[1]*py + Hm[2];
        float hy = Hm[3]*px + Hm[4]*py + Hm[5];
        float hz = Hm[6]*px + Hm[7]*py + Hm[8];
        float ux = ((hx / hz) / IMG_W_) * (float)W_;
        float uy = ((hy / hz) / IMG_H_) * (float)H_;
        float fx = floorf(ux), fy = floorf(uy);
        float wx = ux - fx,  wy = uy - fy;
        valid[n] = (ux >= 0.f && ux <= (float)(W_-1) &&
                    uy >= 0.f && uy <= (float)(H_-1)) ? 1.0f : 0.0f;
        int x0 = min(max((int)fx, 0), W_-1);
        int x1 = min(x0+1, W_-1);
        int y0 = min(max((int)fy, 0), H_-1);
        int y1 = min(y0+1, H_-1);
        float w00 = (1.f-wx)*(1.f-wy), w01 = wx*(1.f-wy);
        float w10 = (1.f-wx)*wy,       w11 = wx*wy;
        const __half* baseh = g_valh + (size_t)bn*P_*DIM + d0;
        uint2 u00 = *(const uint2*)&baseh[(size_t)(y0*W_+x0)*DIM];
        uint2 u01 = *(const uint2*)&baseh[(size_t)(y0*W_+x1)*DIM];
        uint2 u10 = *(const uint2*)&baseh[(size_t)(y1*W_+x0)*DIM];
        uint2 u11 = *(const uint2*)&baseh[(size_t)(y1*W_+x1)*DIM];
        float2 a00a = __half22float2(*(__half2*)&u00.x), a00b = __half22float2(*(__half2*)&u00.y);
        float2 a01a = __half22float2(*(__half2*)&u01.x), a01b = __half22float2(*(__half2*)&u01.y);
        float2 a10a = __half22float2(*(__half2*)&u10.x), a10b = __half22float2(*(__half2*)&u10.y);
        float2 a11a = __half22float2(*(__half2*)&u11.x), a11b = __half22float2(*(__half2*)&u11.y);
        float v0 = a00a.x*w00 + a01a.x*w01 + a10a.x*w10 + a11a.x*w11;
        float v1 = a00a.y*w00 + a01a.y*w01 + a10a.y*w10 + a11a.y*w11;
        float v2 = a00b.x*w00 + a01b.x*w01 + a10b.x*w10 + a11b.x*w11;
        float v3 = a00b.y*w00 + a01b.y*w01 + a10b.y*w10 + a11b.y*w11;
        vb[n][0] = v0; vb[n][1] = v1; vb[n][2] = v2; vb[n][3] = v3;
        ssv[n] = v0*v0 + v1*v1 + v2*v2 + v3*v3;
        ddv[n] = q4.x*v0 + q4.y*v1 + q4.z*v2 + q4.w*v3;
    }
    qs = wsum(qs);
    #pragma unroll
    for (int n = 0; n < N_; n++) { ssv[n] = wsum(ssv[n]); ddv[n] = wsum(ddv[n]); }
    float qinv = 1.0f / fmaxf(sqrtf(qs), 1e-12f);
    float dot[N_];
    #pragma unroll
    for (int n = 0; n < N_; n++)
        dot[n] = ddv[n] * qinv * (1.0f / fmaxf(sqrtf(ssv[n]), 1e-12f)) * valid[n];

    float m = dot[0];
    #pragma unroll
    for (int n = 1; n < N_; n++) m = fmaxf(m, dot[n]);
    float e[N_], s = 0.f;
    #pragma unroll
    for (int n = 0; n < N_; n++) { e[n] = expf(dot[n] - m); s += e[n]; }
    float sinv = 1.0f / s;
    float z[4] = {q4.x, q4.y, q4.z, q4.w};
    #pragma unroll
    for (int n = 0; n < N_; n++) {
        float a = e[n] * sinv;
        #pragma unroll
        for (int i = 0; i < 4; i++) z[i] = fmaf(a, vb[n][i], z[i]);
    }
    float ls = z[0] + z[1] + z[2] + z[3];
    ls = wsum(ls);
    float mean = ls * (1.0f / DIM);
    float vv = 0.f;
    #pragma unroll
    for (int i = 0; i < 4; i++) { float d = z[i] - mean; vv += d*d; }
    vv = wsum(vv);
    float rstd = 1.0f / sqrtf(vv * (1.0f / DIM) + 1e-5f);
    float4 g4 = *(const float4*)&ln1g[d0];
    float4 b4 = *(const float4*)&ln1b[d0];
    float zn[4];
    zn[0] = (z[0]-mean)*rstd*g4.x + b4.x;
    zn[1] = (z[1]-mean)*rstd*g4.y + b4.y;
    zn[2] = (z[2]-mean)*rstd*g4.z + b4.z;
    zn[3] = (z[3]-mean)*rstd*g4.w + b4.w;
    *(float4*)&g_zln[(size_t)pix*DIM + d0] = make_float4(zn[0], zn[1], zn[2], zn[3]);
    *(uint2*)&g_zh[(size_t)pix*DIM + d0] =
        make_uint2(pack2h(__float2half(zn[0]), __float2half(zn[1])),
                   pack2h(__float2half(zn[2]), __float2half(zn[3])));
}

// ---------------- K3: MLP1 (CTA 128tok x 64j, single-B, 3 CTAs/SM) ----------------
__global__ void __launch_bounds__(256, 3) k_mlp1_tc(const float* __restrict__ b1) {
    extern __shared__ __half smh[];
    __half* sA  = smh;                  // 128 x 72
    __half* sBh = smh + 128*TPAD72;     // 64 x 72
    int t = threadIdx.x, wid = t >> 5, lane = t & 31;
    int t0 = blockIdx.x * 128;
    int j0 = blockIdx.y * 64;

    float acc[2][4][4] = {};
    int wm = (wid >> 1) * 32;
    int wn = (wid & 1) * 32;
    const __half* Ag = g_zh + (size_t)t0 * DIM;
    const __half* Bh = g_w1h + (size_t)j0 * DIM;

    #pragma unroll 1
    for (int c = 0; c < 2; c++) {
        if (c) __syncthreads();
        int c0 = c * 64;
        load_rows72(Ag, DIM, c0, sA, 128, t);
        load_rows72(Bh, DIM, c0, sBh, 64, t);
        cpa_commit();
        cpa_wait0();
        __syncthreads();
        gemm64_w32_1(acc, sA, sBh, wm, wn, lane);
    }

    int r0 = wm + (lane >> 2);
    int c0 = wn + (lane & 3) * 2;
    #pragma unroll
    for (int mt = 0; mt < 2; mt++)
        #pragma unroll
        for (int nt = 0; nt < 4; nt++) {
            int row = r0 + mt*16, col = c0 + nt*8;
            float bj0 = b1[j0 + col], bj1 = b1[j0 + col + 1];
            float v00 = gelu_exact(acc[mt][nt][0] + bj0);
            float v01 = gelu_exact(acc[mt][nt][1] + bj1);
            float v10 = gelu_exact(acc[mt][nt][2] + bj0);
            float v11 = gelu_exact(acc[mt][nt][3] + bj1);
            *(uint32_t*)&g_hh[(size_t)(t0+row)*(2*DIM) + j0 + col] =
                pack2h(__float2half(v00), __float2half(v01));
            *(uint32_t*)&g_hh[(size_t)(t0+row+8)*(2*DIM) + j0 + col] =
                pack2h(__float2half(v10), __float2half(v11));
        }
}

// ---------------- K4: MLP2 (CTA 64tok x 128d, single-B, 3 CTAs/SM) + residual + LN2 ----------------
__global__ void __launch_bounds__(256, 3) k_mlp2_tc(const float* __restrict__ b2,
                                                    const float* __restrict__ g2,
                                                    const float* __restrict__ bb2,
                                                    float* __restrict__ out) {
    extern __shared__ __half smh[];
    __half* sA  = smh;                  // 64 x 72
    __half* sBh = smh + 64*TPAD72;      // 128 x 72
    int t = threadIdx.x, wid = t >> 5, lane = t & 31;
    int t0 = blockIdx.x * 64;

    float acc[2][4][4] = {};
    int wm = (wid >> 2) * 32;
    int wn = (wid & 3) * 32;
    const __half* Ag = g_hh + (size_t)t0 * (2*DIM);

    #pragma unroll 1
    for (int c = 0; c < 4; c++) {
        if (c) __syncthreads();
        int c0 = c * 64;
        load_rows72(Ag,    2*DIM, c0, sA,   64, t);
        load_rows72(g_w2h, 2*DIM, c0, sBh, 128, t);
        cpa_commit();
        cpa_wait0();
        __syncthreads();
        gemm64_w32_1(acc, sA, sBh, wm, wn, lane);
    }
    __syncthreads();   // smem reuse

    float* smT   = (float*)smh;         // [64][129] fp32 = 33024 B
    float* sMean = smT + 64*129;
    float* sRstd = sMean + 64;
    const float* zb = g_zln + (size_t)t0 * DIM;
    int r0 = wm + (lane >> 2);
    int c0 = wn + (lane & 3) * 2;
    #pragma unroll
    for (int mt = 0; mt < 2; mt++)
        #pragma unroll
        for (int nt = 0; nt < 4; nt++) {
            int row = r0 + mt*16, col = c0 + nt*8;
            float b20 = b2[col], b21 = b2[col+1];
            float2 z0 = *(const float2*)&zb[(size_t)row*DIM + col];
            float2 z1 = *(const float2*)&zb[(size_t)(row+8)*DIM + col];
            smT[row*129 + col]       = acc[mt][nt][0] + b20 + z0.x;
            smT[row*129 + col + 1]   = acc[mt][nt][1] + b21 + z0.y;
            smT[(row+8)*129 + col]   = acc[mt][nt][2] + b20 + z1.x;
            smT[(row+8)*129 + col+1] = acc[mt][nt][3] + b21 + z1.y;
        }
    __syncthreads();
    if (t < 64) {
        float s = 0.f, q = 0.f;
        #pragma unroll 8
        for (int c = 0; c < 128; c++) {
            float v = smT[t*129 + c];
            s += v; q += v*v;
        }
        float mean = s * (1.0f / DIM);
        float var  = fmaxf(q * (1.0f / DIM) - mean*mean, 0.0f);
        sMean[t] = mean;
        sRstd[t] = 1.0f / sqrtf(var + 1e-5f);
    }
    __syncthreads();
    int b = t0 / P_;
    int prem = t0 - b * P_;
    #pragma unroll 4
    for (int k = 0; k < 32; k++) {
        int idx = k * 256 + t;
        int d = idx >> 6, p = idx & 63;   // consecutive t -> consecutive p
        float v = smT[p*129 + d];
        out[((size_t)(b*DIM + d))*P_ + prem + p] =
            (v - sMean[p]) * sRstd[p] * g2[d] + bb2[d];
    }
}

// ---------------- launch ----------------
extern "C" void kernel_launch(void* const* d_in, const int* in_sizes, int n_in,
                              void* d_out, int out_size) {
    const float* feature   = (const float*)d_in[0];
    const float* I_src     = (const float*)d_in[1];
    const float* I_tar_inv = (const float*)d_in[2];
    const float* E         = (const float*)d_in[3];
    const float* dis       = (const float*)d_in[4];
    const float* nrm       = (const float*)d_in[5];
    const float* conv_w    = (const float*)d_in[6];
    const float* bn_gamma  = (const float*)d_in[7];
    const float* bn_beta   = (const float*)d_in[8];
    const float* bn_mean   = (const float*)d_in[9];
    const float* bn_var    = (const float*)d_in[10];
    const float* ln1_g     = (const float*)d_in[11];
    const float* ln1_b     = (const float*)d_in[12];
    const float* ln2_g     = (const float*)d_in[13];
    const float* ln2_b     = (const float*)d_in[14];
    const float* mlp_w1    = (const float*)d_in[15];
    const float* mlp_b1    = (const float*)d_in[16];
    const float* mlp_w2    = (const float*)d_in[17];
    const float* mlp_b2    = (const float*)d_in[18];
    float* out = (float*)d_out;

    cudaFuncSetAttribute(k_conv_tc, cudaFuncAttributeMaxDynamicSharedMemorySize, SMEM_CONV);
    cudaFuncSetAttribute(k_mlp1_tc, cudaFuncAttributeMaxDynamicSharedMemorySize, SMEM_MLP1);
    cudaFuncSetAttribute(k_mlp2_tc, cudaFuncAttributeMaxDynamicSharedMemorySize, SMEM_MLP2);

    k_setup<<<48, 256>>>(I_src, I_tar_inv, E, dis, nrm, conv_w,
                         bn_gamma, bn_beta, bn_mean, bn_var, mlp_w1, mlp_w2);
    k_conv_tc<<<dim3(P_/128, BNV), 256, SMEM_CONV>>>(feature);
    k_attn<<<T2/8, 256>>>(ln1_g, ln1_b);
    k_mlp1_tc<<<dim3(T2/128, 4), 256, SMEM_MLP1>>>(mlp_b1);
    k_mlp2_tc<<<T2/64, 256, SMEM_MLP2>>>(mlp_b2, ln2_g, ln2_b, out);
}